// round 8
// baseline (speedup 1.0000x reference)
#include <cuda_runtime.h>
#include <cstdint>

#define BATCH 4
#define T 1024
#define D 64
#define H 2
#define HD 32
#define DFF 256
#define NL 4
#define VOCAB 8192
#define BT (BATCH*T)

// ---------------- device scratch (no allocs allowed) ----------------
__device__ __align__(16) int8_t  g_x[BT*D];
__device__ __align__(16) int8_t  g_h[BT*D];
__device__ __align__(16) int8_t  g_q[BT*D];
__device__ __align__(16) int8_t  g_k[BT*D];
__device__ __align__(16) int8_t  g_v[BT*D];
__device__ __align__(16) int8_t  g_a[BT*D];
__device__ __align__(16) int8_t  g_wq[NL*D*D], g_wk[NL*D*D], g_wv[NL*D*D], g_wo[NL*D*D];
__device__ __align__(16) int8_t  g_wup[NL*DFF*D], g_wdn[NL*D*DFF];
__device__ __align__(16) int     g_gattn[NL*D], g_gff[NL*D], g_gfin[D];
__device__ __align__(16) int8_t  g_ehi[VOCAB*D];
__device__ __align__(16) uint8_t g_elo[VOCAB*D];

// ---------------- helpers ----------------
__device__ __forceinline__ int wrap8(int v){ return (int)(signed char)(v & 0xff); }
__device__ __forceinline__ int clampi(int v,int lo,int hi){ return min(max(v,lo),hi); }
__device__ __forceinline__ int gammaq(float w){
    float c = fminf(fmaxf(w,-2.f),2.f);
    float r = rintf(__fmul_rn(c,1024.f));
    return clampi((int)r,-32768,32767);
}
__device__ __forceinline__ void rms_pair(int x0,int x1,int g0,int g1,int& y0,int& y1){
    int ss = x0*x0 + x1*x1;
    #pragma unroll
    for(int o=16;o>0;o>>=1) ss += __shfl_xor_sync(0xffffffffu, ss, o);
    int mean_sq = ss >> 6;
    int lut = min(mean_sq >> 6, 255);
    float bc = (float)(lut*64 + 32);
    int inv = clampi((int)rintf(__fdiv_rn(16384.f, __fsqrt_rn(bc))), 0, 16383);
    int p0 = (x0*inv) >> 8, p1 = (x1*inv) >> 8;
    y0 = clampi((int)floorf(__fmul_rn(__fmul_rn((float)p0,(float)g0), 0.0009765625f)),-128,127);
    y1 = clampi((int)floorf(__fmul_rn(__fmul_rn((float)p1,(float)g1), 0.0009765625f)),-128,127);
}
// m16n8k32 int8 MMA
__device__ __forceinline__ void mma_s8s8(int* d, const int* a, const int* b){
    asm("mma.sync.aligned.m16n8k32.row.col.s32.s8.s8.s32 "
        "{%0,%1,%2,%3},{%4,%5,%6,%7},{%8,%9},{%0,%1,%2,%3};"
        : "+r"(d[0]),"+r"(d[1]),"+r"(d[2]),"+r"(d[3])
        : "r"(a[0]),"r"(a[1]),"r"(a[2]),"r"(a[3]),"r"(b[0]),"r"(b[1]));
}
__device__ __forceinline__ void mma_s8u8(int* d, const int* a, const int* b){
    asm("mma.sync.aligned.m16n8k32.row.col.s32.s8.u8.s32 "
        "{%0,%1,%2,%3},{%4,%5,%6,%7},{%8,%9},{%0,%1,%2,%3};"
        : "+r"(d[0]),"+r"(d[1]),"+r"(d[2]),"+r"(d[3])
        : "r"(a[0]),"r"(a[1]),"r"(a[2]),"r"(a[3]),"r"(b[0]),"r"(b[1]));
}
__device__ __forceinline__ void mma_u8s8(int* d, const unsigned* a, const int* b){
    asm("mma.sync.aligned.m16n8k32.row.col.s32.u8.s8.s32 "
        "{%0,%1,%2,%3},{%4,%5,%6,%7},{%8,%9},{%0,%1,%2,%3};"
        : "+r"(d[0]),"+r"(d[1]),"+r"(d[2]),"+r"(d[3])
        : "r"(a[0]),"r"(a[1]),"r"(a[2]),"r"(a[3]),"r"(b[0]),"r"(b[1]));
}

// ---------------- merged prep: weight ternarization + emb/gamma quant ----------------
__global__ void prep_all(const float* qw, const float* kw, const float* vw,
                         const float* ow, const float* up, const float* dn,
                         const float* tok_emb, const float* attn_nw,
                         const float* ff_nw, const float* fin_nw){
    int m = blockIdx.x;
    if(m < 24){
        const float* src; int8_t* dst; int n;
        if(m < 16){
            int l = m >> 2, wsel = m & 3; n = D*D;
            const float* bases[4] = {qw,kw,vw,ow};
            int8_t* dsts[4] = {g_wq,g_wk,g_wv,g_wo};
            src = bases[wsel] + l*n; dst = dsts[wsel] + l*n;
        } else if(m < 20){ int l=m-16; n=DFF*D; src=up+l*n; dst=g_wup+l*n; }
        else             { int l=m-20; n=D*DFF; src=dn+l*n; dst=g_wdn+l*n; }

        __shared__ float red[256];
        float s = 0.f;
        for(int i=threadIdx.x;i<n;i+=256) s += fabsf(src[i]);
        red[threadIdx.x]=s; __syncthreads();
        for(int o=128;o>0;o>>=1){ if(threadIdx.x<o) red[threadIdx.x]+=red[threadIdx.x+o]; __syncthreads(); }
        float scale = fmaxf(__fdiv_rn(red[0], (float)n), 1e-5f);
        for(int i=threadIdx.x;i<n;i+=256){
            float t = rintf(__fdiv_rn(src[i], scale));
            t = fminf(fmaxf(t,-1.f),1.f);
            dst[i] = (int8_t)(int)t;
        }
        return;
    }
    int i = (m-24)*256 + threadIdx.x;
    if(i < VOCAB*D){
        float r = rintf(__fmul_rn(tok_emb[i],1024.f));
        int q = clampi((int)r,-32768,32767);
        g_ehi[i] = (int8_t)(q >> 8);
        g_elo[i] = (uint8_t)(q & 0xff);
    }
    if(m == 24){
        int t=threadIdx.x;
        for(int j=t;j<NL*D;j+=256){
            g_gattn[j] = gammaq(attn_nw[j]);
            g_gff[j]   = gammaq(ff_nw[j]);
        }
        if(t<D) g_gfin[t] = gammaq(fin_nw[t]);
    }
}

// ---------------- token+pos embedding ----------------
__global__ void embed_kernel(const int* tokens, const float* tok_emb, const float* pos_emb){
    int i = blockIdx.x*256 + threadIdx.x;
    if(i >= BT*D) return;
    int bt = i >> 6, d = i & 63;
    int t = bt & (T-1);
    int tok = tokens[bt];
    int tq = clampi((int)rintf(__fmul_rn(tok_emb[tok*D+d],1024.f)),-32768,32767);
    int pq = clampi((int)rintf(__fmul_rn(pos_emb[t*D+d],1024.f)),-32768,32767);
    g_x[i] = (int8_t)wrap8((tq+pq) >> 3);
}

// ---------------- final rmsnorm (x -> g_h), one warp per row ----------------
__global__ void rmsnorm_final_kernel(){
    int row  = (blockIdx.x*blockDim.x + threadIdx.x) >> 5;
    int lane = threadIdx.x & 31;
    if(row >= BT) return;
    const int8_t* r = g_x + row*D;
    int x0 = r[lane*2], x1 = r[lane*2+1];
    int y0,y1;
    rms_pair(x0,x1,g_gfin[lane*2],g_gfin[lane*2+1],y0,y1);
    g_h[row*D+lane*2]   = (int8_t)y0;
    g_h[row*D+lane*2+1] = (int8_t)y1;
}

// ---------------- fused rmsnorm + QKV via MMA: 16 tokens per block ----------------
__global__ __launch_bounds__(256) void qkv_norm_kernel(int layer){
    __shared__ uint8_t shb[16*68];
    int tid = threadIdx.x, warp = tid>>5, lane = tid&31;
    int g = lane>>2, tg = lane&3;
    int bt0 = blockIdx.x*16;
    const int* gm = g_gattn + layer*D;
    // rmsnorm: warp handles tokens 2*warp, 2*warp+1
    #pragma unroll
    for(int t=0;t<2;t++){
        int tok = 2*warp + t;
        const int8_t* xr = g_x + (bt0+tok)*D;
        int x0 = xr[2*lane], x1 = xr[2*lane+1];
        int y0,y1;
        rms_pair(x0,x1,gm[2*lane],gm[2*lane+1],y0,y1);
        shb[tok*68 + 2*lane]   = (uint8_t)(y0 & 0xff);
        shb[tok*68 + 2*lane+1] = (uint8_t)(y1 & 0xff);
    }
    __syncthreads();
    // A fragments (16 tokens x K=64), pitch 17 ints
    const int* shi = (const int*)shb;
    int a[2][4];
    #pragma unroll
    for(int kc=0;kc<2;kc++){
        a[kc][0] = shi[g*17     + kc*8 + tg];
        a[kc][1] = shi[(g+8)*17 + kc*8 + tg];
        a[kc][2] = shi[g*17     + kc*8 + 4 + tg];
        a[kc][3] = shi[(g+8)*17 + kc*8 + 4 + tg];
    }
    const int* wq = (const int*)(g_wq + layer*D*D);
    const int* wk = (const int*)(g_wk + layer*D*D);
    const int* wv = (const int*)(g_wv + layer*D*D);
    #pragma unroll
    for(int nt=0;nt<3;nt++){
        const int* wb = (nt==0) ? wq : (nt==1 ? wk : wv);
        int8_t* dst   = (nt==0) ? g_q : (nt==1 ? g_k : g_v);
        int c = warp*8 + g;            // B-frag col within 0..63
        int d[4] = {0,0,0,0};
        #pragma unroll
        for(int kc=0;kc<2;kc++){
            int b[2] = { wb[c*16 + kc*8 + tg], wb[c*16 + kc*8 + 4 + tg] };
            mma_s8s8(d, a[kc], b);
        }
        int o0 = warp*8 + 2*tg;
        int v0 = clampi(d[0]>>6,-128,127) & 0xff, v1 = clampi(d[1]>>6,-128,127) & 0xff;
        int v2 = clampi(d[2]>>6,-128,127) & 0xff, v3 = clampi(d[3]>>6,-128,127) & 0xff;
        *(uint16_t*)(dst + (bt0+g)*64   + o0) = (uint16_t)(v0 | (v1<<8));
        *(uint16_t*)(dst + (bt0+g+8)*64 + o0) = (uint16_t)(v2 | (v3<<8));
    }
}

// ---------------- fused attention: scores + LUT softmax + MMA AV ----------------
#define SK_WORDS   (T*8)
#define SVT_PITCH  33
#define SVT_WORDS  ((T/4)*SVT_PITCH)
#define SP_PITCH   1040
#define SP_BYTES   (8*SP_PITCH)
#define ATTN_SMEM  ((SK_WORDS+SVT_WORDS)*4 + SP_BYTES + 256*4)
__device__ __forceinline__ int ksw(int k,int w){ return k*8 + (w ^ ((k>>2)&7)); }

__global__ __launch_bounds__(256) void attn_fused_kernel(){
    extern __shared__ unsigned dyn[];
    unsigned* sK  = dyn;
    unsigned* sVT = dyn + SK_WORDS;
    uint8_t*  sP  = (uint8_t*)(dyn + SK_WORDS + SVT_WORDS);
    int*      sred = (int*)(sP + SP_BYTES);
    int bh = blockIdx.y; int b = bh>>1, h = bh&1;
    int warp = threadIdx.x>>5, lane = threadIdx.x&31;
    int g = lane>>2, tg = lane&3;

    int jmaxb = (blockIdx.x*8+7)>>5;
    int KN = (jmaxb+1)*32;

    const unsigned* kb = (const unsigned*)g_k + (b*T)*16 + h*8;
    const unsigned* vb = (const unsigned*)g_v + (b*T)*16 + h*8;
    uint8_t* svb = (uint8_t*)sVT;
    for(int idx=threadIdx.x; idx<KN*8; idx+=256){
        int k = idx>>3, w = idx&7;
        sK[ksw(k,w)] = kb[k*16+w];
        unsigned u = vb[k*16+w];
        int c = k>>2, r = k&3, d0 = w*4;
        svb[c*(SVT_PITCH*4) + (d0+0)*4 + r] = (uint8_t)( u        & 0xff);
        svb[c*(SVT_PITCH*4) + (d0+1)*4 + r] = (uint8_t)((u >> 8)  & 0xff);
        svb[c*(SVT_PITCH*4) + (d0+2)*4 + r] = (uint8_t)((u >> 16) & 0xff);
        svb[c*(SVT_PITCH*4) + (d0+3)*4 + r] = (uint8_t)((u >> 24) & 0xff);
    }
    __syncthreads();

    int q = blockIdx.x*8 + warp;
    const unsigned* qv = (const unsigned*)g_q + (b*T+q)*16 + h*8;
    unsigned qr[8];
    #pragma unroll
    for(int w=0;w<8;w++) qr[w] = qv[w];

    const int NEG = (int)0x80000000;
    int sc[32];
    int mx = NEG;
    #pragma unroll
    for(int j=0;j<32;j++){
        sc[j] = NEG;
        if(j > jmaxb) break;
        int k = j*32 + lane;
        if(k <= q){
            int acc = 0;
            #pragma unroll
            for(int w=0;w<8;w++) acc = __dp4a((int)qr[w], (int)sK[ksw(k,w)], acc);
            float p = __int2float_rn(acc*45);
            int s = (int)floorf(__fmul_rn(p, 0.00390625f));
            sc[j] = s; mx = max(mx, s);
        }
    }
    #pragma unroll
    for(int o=16;o>0;o>>=1) mx = max(mx, __shfl_xor_sync(0xffffffffu, mx, o));

    int sh_l = lane - 24;
    int ea_l = (sh_l>=-3) ? 256 + sh_l*64
             : (sh_l>=-8) ? 64 + (sh_l+3)*11
             : sh_l + 24;
    if(lane > 24) ea_l = 0;

    int su = 0;
    #pragma unroll
    for(int j=0;j<32;j++){
        if(j > jmaxb) break;
        bool valid = (sc[j] != NEG);
        int idx = valid ? (sc[j] - mx + 24) : -1;
        int idxc = clampi(idx, 0, 31);
        int ea = __shfl_sync(0xffffffffu, ea_l, idxc);
        if(!(valid && idx >= 0)) ea = 0;
        su += ea;
        sc[j] = (valid && idx >= 0) ? idx : 32;
    }
    #pragma unroll
    for(int o=16;o>0;o>>=1) su += __shfl_xor_sync(0xffffffffu, su, o);
    float sf = (float)max(su, 1);

    int p_l = 0;
    if(ea_l > 0)
        p_l = clampi((int)rintf(__fmul_rn(__fdiv_rn((float)ea_l, sf), 255.f)), 0, 255);

    uint8_t* prow = sP + warp*SP_PITCH;
    #pragma unroll
    for(int j=0;j<32;j++){
        if(j > jmaxb) break;
        int idx = sc[j];
        int p = __shfl_sync(0xffffffffu, p_l, idx & 31);
        if(idx >= 32) p = 0;
        prow[j*32+lane] = (uint8_t)p;
    }
    __syncthreads();

    int nt = warp & 3, half = warp >> 2;
    int dim = nt*8 + g;
    int dacc[4] = {0,0,0,0};
    for(int c32 = half; c32 <= jmaxb; c32 += 2){
        const uint8_t* pr = sP + g*SP_PITCH + c32*32;
        unsigned A[4];
        A[0] = *(const unsigned*)(pr + tg*4);
        A[1] = A[0];
        A[2] = *(const unsigned*)(pr + 16 + tg*4);
        A[3] = A[2];
        int Bv[2];
        Bv[0] = (int)sVT[(c32*8 + tg)*SVT_PITCH + dim];
        Bv[1] = (int)sVT[(c32*8 + 4 + tg)*SVT_PITCH + dim];
        mma_u8s8(dacc, A, Bv);
    }
    if(half == 1){
        sred[nt*64 + g*8 + 2*tg]     = dacc[0];
        sred[nt*64 + g*8 + 2*tg + 1] = dacc[1];
    }
    __syncthreads();
    if(half == 0){
        int v0 = dacc[0] + sred[nt*64 + g*8 + 2*tg];
        int v1 = dacc[1] + sred[nt*64 + g*8 + 2*tg + 1];
        int qq = blockIdx.x*8 + g;
        int o0 = wrap8(v0>>8) & 0xff, o1 = wrap8(v1>>8) & 0xff;
        *(uint16_t*)(g_a + (b*T+qq)*64 + h*32 + nt*8 + 2*tg) = (uint16_t)(o0 | (o1<<8));
    }
}

// ---------------- fused oproj+residual+rmsnorm+FFN+residual via MMA: 16 tokens ----------------
__global__ __launch_bounds__(256) void ffn_fused_kernel(int layer){
    __shared__ int      sa[16*17];
    __shared__ uint8_t  sxb[16*64];
    __shared__ uint8_t  shb[16*68];
    __shared__ uint8_t  sub[16*260];
    int tid = threadIdx.x, warp = tid>>5, lane = tid&31;
    int g = lane>>2, tg = lane&3;
    int bt0 = blockIdx.x*16;

    {   // stage g_a (16 tokens x 16 words)
        int tok = tid>>4, i = tid&15;
        sa[tok*17+i] = ((const int*)g_a)[(bt0+tok)*16 + i];
    }
    __syncthreads();

    // ---- oproj MMA: warp -> 8-col tile ----
    {
        int a[2][4];
        #pragma unroll
        for(int kc=0;kc<2;kc++){
            a[kc][0] = sa[g*17     + kc*8 + tg];
            a[kc][1] = sa[(g+8)*17 + kc*8 + tg];
            a[kc][2] = sa[g*17     + kc*8 + 4 + tg];
            a[kc][3] = sa[(g+8)*17 + kc*8 + 4 + tg];
        }
        const int* wo = (const int*)(g_wo + layer*D*D);
        int c = warp*8 + g;
        int d[4] = {0,0,0,0};
        #pragma unroll
        for(int kc=0;kc<2;kc++){
            int b[2] = { wo[c*16 + kc*8 + tg], wo[c*16 + kc*8 + 4 + tg] };
            mma_s8s8(d, a[kc], b);
        }
        int o0 = warp*8 + 2*tg;
        int r0 = clampi(d[0]>>6,-128,127), r1 = clampi(d[1]>>6,-128,127);
        int r2 = clampi(d[2]>>6,-128,127), r3 = clampi(d[3]>>6,-128,127);
        sxb[g*64 + o0]       = (uint8_t)(wrap8((int)g_x[(bt0+g)*64 + o0]     + r0) & 0xff);
        sxb[g*64 + o0+1]     = (uint8_t)(wrap8((int)g_x[(bt0+g)*64 + o0+1]   + r1) & 0xff);
        sxb[(g+8)*64 + o0]   = (uint8_t)(wrap8((int)g_x[(bt0+g+8)*64 + o0]   + r2) & 0xff);
        sxb[(g+8)*64 + o0+1] = (uint8_t)(wrap8((int)g_x[(bt0+g+8)*64 + o0+1] + r3) & 0xff);
    }
    __syncthreads();

    // ---- rmsnorm: warp handles tokens 2w, 2w+1 ----
    {
        const int* gm = g_gff + layer*D;
        #pragma unroll
        for(int t=0;t<2;t++){
            int tok = 2*warp + t;
            int x0 = (int)(int8_t)sxb[tok*64 + 2*lane];
            int x1 = (int)(int8_t)sxb[tok*64 + 2*lane+1];
            int y0,y1;
            rms_pair(x0,x1,gm[2*lane],gm[2*lane+1],y0,y1);
            shb[tok*68 + 2*lane]   = (uint8_t)(y0 & 0xff);
            shb[tok*68 + 2*lane+1] = (uint8_t)(y1 & 0xff);
        }
    }
    __syncthreads();

    // ---- up + relu MMA: warp -> 4 x 8-col tiles (N=256) ----
    {
        const int* shi = (const int*)shb;
        int a[2][4];
        #pragma unroll
        for(int kc=0;kc<2;kc++){
            a[kc][0] = shi[g*17     + kc*8 + tg];
            a[kc][1] = shi[(g+8)*17 + kc*8 + tg];
            a[kc][2] = shi[g*17     + kc*8 + 4 + tg];
            a[kc][3] = shi[(g+8)*17 + kc*8 + 4 + tg];
        }
        const int* wu = (const int*)(g_wup + layer*DFF*D);
        #pragma unroll
        for(int nt=0;nt<4;nt++){
            int colb = warp*32 + nt*8;
            int c = colb + g;
            int d[4] = {0,0,0,0};
            #pragma unroll
            for(int kc=0;kc<2;kc++){
                int b[2] = { wu[c*16 + kc*8 + tg], wu[c*16 + kc*8 + 4 + tg] };
                mma_s8s8(d, a[kc], b);
            }
            int c0 = colb + 2*tg;
            int u0 = max(clampi(d[0]>>6,-128,127),0), u1 = max(clampi(d[1]>>6,-128,127),0);
            int u2 = max(clampi(d[2]>>6,-128,127),0), u3 = max(clampi(d[3]>>6,-128,127),0);
            sub[g*260 + c0]       = (uint8_t)u0;
            sub[g*260 + c0+1]     = (uint8_t)u1;
            sub[(g+8)*260 + c0]   = (uint8_t)u2;
            sub[(g+8)*260 + c0+1] = (uint8_t)u3;
        }
    }
    __syncthreads();

    // ---- down MMA (K=256): warp -> 8-col tile ----
    {
        const int* sui = (const int*)sub;
        const int* wd = (const int*)(g_wdn + layer*D*DFF);
        int c = warp*8 + g;
        int d[4] = {0,0,0,0};
        #pragma unroll
        for(int kc=0;kc<8;kc++){
            int a[4];
            a[0] = sui[g*65     + kc*8 + tg];
            a[1] = sui[(g+8)*65 + kc*8 + tg];
            a[2] = sui[g*65     + kc*8 + 4 + tg];
            a[3] = sui[(g+8)*65 + kc*8 + 4 + tg];
            int b[2] = { wd[c*64 + kc*8 + tg], wd[c*64 + kc*8 + 4 + tg] };
            mma_s8s8(d, a, b);
        }
        int o0 = warp*8 + 2*tg;
        int r0 = clampi(d[0]>>6,-128,127), r1 = clampi(d[1]>>6,-128,127);
        int r2 = clampi(d[2]>>6,-128,127), r3 = clampi(d[3]>>6,-128,127);
        g_x[(bt0+g)*64 + o0]     = (int8_t)wrap8((int)(int8_t)sxb[g*64 + o0]       + r0);
        g_x[(bt0+g)*64 + o0+1]   = (int8_t)wrap8((int)(int8_t)sxb[g*64 + o0+1]     + r1);
        g_x[(bt0+g+8)*64 + o0]   = (int8_t)wrap8((int)(int8_t)sxb[(g+8)*64 + o0]   + r2);
        g_x[(bt0+g+8)*64 + o0+1] = (int8_t)wrap8((int)(int8_t)sxb[(g+8)*64 + o0+1] + r3);
    }
}

// ---------------- logits via IMMA: warp = 64 tokens x 32 vocab ----------------
__global__ __launch_bounds__(256) void logits_mma_kernel(float* __restrict__ out){
    int warp = threadIdx.x>>5, lane = threadIdx.x&31;
    int g = lane>>2, tg = lane&3;
    int vbase = blockIdx.x*256 + warp*32;
    int mbase = blockIdx.y*64;

    int bhi[4][2][2], blo[4][2][2];
    #pragma unroll
    for(int nt=0;nt<4;nt++){
        int col = vbase + nt*8 + g;
        const int8_t*  eh = g_ehi + col*64;
        const uint8_t* el = g_elo + col*64;
        #pragma unroll
        for(int kc=0;kc<2;kc++){
            bhi[nt][kc][0] = *(const int*)(eh + kc*32 + tg*4);
            bhi[nt][kc][1] = *(const int*)(eh + kc*32 + 16 + tg*4);
            blo[nt][kc][0] = *(const int*)(el + kc*32 + tg*4);
            blo[nt][kc][1] = *(const int*)(el + kc*32 + 16 + tg*4);
        }
    }
    #pragma unroll
    for(int mt=0;mt<4;mt++){
        int row0 = mbase + mt*16 + g;
        const int8_t* h0 = g_h + row0*64;
        const int8_t* h8 = g_h + (row0+8)*64;
        int a[2][4];
        #pragma unroll
        for(int kc=0;kc<2;kc++){
            a[kc][0] = *(const int*)(h0 + kc*32 + tg*4);
            a[kc][1] = *(const int*)(h8 + kc*32 + tg*4);
            a[kc][2] = *(const int*)(h0 + kc*32 + 16 + tg*4);
            a[kc][3] = *(const int*)(h8 + kc*32 + 16 + tg*4);
        }
        #pragma unroll
        for(int nt=0;nt<4;nt++){
            int dh[4]={0,0,0,0}, dl[4]={0,0,0,0};
            #pragma unroll
            for(int kc=0;kc<2;kc++){
                mma_s8s8(dh, a[kc], bhi[nt][kc]);
                mma_s8u8(dl, a[kc], blo[nt][kc]);
            }
            int col = vbase + nt*8 + 2*tg;
            float2 v0, v1;
            v0.x = __fmul_rn((float)(dh[0]*256+dl[0]), 1.220703125e-4f);
            v0.y = __fmul_rn((float)(dh[1]*256+dl[1]), 1.220703125e-4f);
            v1.x = __fmul_rn((float)(dh[2]*256+dl[2]), 1.220703125e-4f);
            v1.y = __fmul_rn((float)(dh[3]*256+dl[3]), 1.220703125e-4f);
            *(float2*)(out + (size_t)row0*VOCAB + col)     = v0;
            *(float2*)(out + (size_t)(row0+8)*VOCAB + col) = v1;
        }
    }
}

// ---------------- launch ----------------
extern "C" void kernel_launch(void* const* d_in, const int* in_sizes, int n_in,
                              void* d_out, int out_size){
    const int*   tokens  = (const int*)  d_in[0];
    const float* tok_emb = (const float*)d_in[1];
    const float* pos_emb = (const float*)d_in[2];
    const float* attn_nw = (const float*)d_in[3];
    const float* qw      = (const float*)d_in[4];
    const float* kw      = (const float*)d_in[5];
    const float* vw      = (const float*)d_in[6];
    const float* ow      = (const float*)d_in[7];
    const float* ff_nw   = (const float*)d_in[8];
    const float* up      = (const float*)d_in[9];
    const float* dn      = (const float*)d_in[10];
    const float* fin_nw  = (const float*)d_in[11];
    float* out = (float*)d_out;

    cudaFuncSetAttribute(attn_fused_kernel,
                         cudaFuncAttributeMaxDynamicSharedMemorySize, ATTN_SMEM);

    prep_all<<<24 + (VOCAB*D+255)/256, 256>>>(qw,kw,vw,ow,up,dn,
                                              tok_emb, attn_nw, ff_nw, fin_nw);
    embed_kernel<<<(BT*D+255)/256,256>>>(tokens, tok_emb, pos_emb);

    for(int l=0;l<NL;l++){
        qkv_norm_kernel<<<BT/16,256>>>(l);
        attn_fused_kernel<<<dim3(T/8, BATCH*H),256,ATTN_SMEM>>>();
        ffn_fused_kernel<<<BT/16,256>>>(l);
    }
    rmsnorm_final_kernel<<<BT/8,256>>>();
    logits_mma_kernel<<<dim3(VOCAB/256, BT/64),256>>>(out);
}

// round 9
// speedup vs baseline: 1.0700x; 1.0700x over previous
#include <cuda_runtime.h>
#include <cstdint>

#define BATCH 4
#define T 1024
#define D 64
#define H 2
#define HD 32
#define DFF 256
#define NL 4
#define VOCAB 8192
#define BT (BATCH*T)

// ---------------- device scratch (no allocs allowed) ----------------
__device__ __align__(16) int8_t  g_x[BT*D];
__device__ __align__(16) int8_t  g_h[BT*D];
__device__ __align__(16) int8_t  g_q[BT*D];
__device__ __align__(16) int8_t  g_k[BT*D];
__device__ __align__(16) int8_t  g_a[BT*D];
__device__ __align__(16) int8_t  g_vt[BATCH*H*(T/4)*HD*4];  // V transposed quad-packed
__device__ __align__(16) int8_t  g_wq[NL*D*D], g_wk[NL*D*D], g_wv[NL*D*D], g_wo[NL*D*D];
__device__ __align__(16) int8_t  g_wup[NL*DFF*D], g_wdn[NL*D*DFF];
__device__ __align__(16) int     g_gattn[NL*D], g_gff[NL*D], g_gfin[D];
__device__ __align__(16) int8_t  g_ehi[VOCAB*D];
__device__ __align__(16) uint8_t g_elo[VOCAB*D];

// ---------------- helpers ----------------
__device__ __forceinline__ int wrap8(int v){ return (int)(signed char)(v & 0xff); }
__device__ __forceinline__ int clampi(int v,int lo,int hi){ return min(max(v,lo),hi); }
__device__ __forceinline__ int gammaq(float w){
    float c = fminf(fmaxf(w,-2.f),2.f);
    float r = rintf(__fmul_rn(c,1024.f));
    return clampi((int)r,-32768,32767);
}
__device__ __forceinline__ void rms_pair(int x0,int x1,int g0,int g1,int& y0,int& y1){
    int ss = x0*x0 + x1*x1;
    #pragma unroll
    for(int o=16;o>0;o>>=1) ss += __shfl_xor_sync(0xffffffffu, ss, o);
    int mean_sq = ss >> 6;
    int lut = min(mean_sq >> 6, 255);
    float bc = (float)(lut*64 + 32);
    int inv = clampi((int)rintf(__fdiv_rn(16384.f, __fsqrt_rn(bc))), 0, 16383);
    int p0 = (x0*inv) >> 8, p1 = (x1*inv) >> 8;
    y0 = clampi((int)floorf(__fmul_rn(__fmul_rn((float)p0,(float)g0), 0.0009765625f)),-128,127);
    y1 = clampi((int)floorf(__fmul_rn(__fmul_rn((float)p1,(float)g1), 0.0009765625f)),-128,127);
}
// m16n8k32 int8 MMA
__device__ __forceinline__ void mma_s8s8(int* d, const int* a, const int* b){
    asm("mma.sync.aligned.m16n8k32.row.col.s32.s8.s8.s32 "
        "{%0,%1,%2,%3},{%4,%5,%6,%7},{%8,%9},{%0,%1,%2,%3};"
        : "+r"(d[0]),"+r"(d[1]),"+r"(d[2]),"+r"(d[3])
        : "r"(a[0]),"r"(a[1]),"r"(a[2]),"r"(a[3]),"r"(b[0]),"r"(b[1]));
}
__device__ __forceinline__ void mma_s8u8(int* d, const int* a, const int* b){
    asm("mma.sync.aligned.m16n8k32.row.col.s32.s8.u8.s32 "
        "{%0,%1,%2,%3},{%4,%5,%6,%7},{%8,%9},{%0,%1,%2,%3};"
        : "+r"(d[0]),"+r"(d[1]),"+r"(d[2]),"+r"(d[3])
        : "r"(a[0]),"r"(a[1]),"r"(a[2]),"r"(a[3]),"r"(b[0]),"r"(b[1]));
}
__device__ __forceinline__ void mma_u8s8(int* d, const unsigned* a, const int* b){
    asm("mma.sync.aligned.m16n8k32.row.col.s32.u8.s8.s32 "
        "{%0,%1,%2,%3},{%4,%5,%6,%7},{%8,%9},{%0,%1,%2,%3};"
        : "+r"(d[0]),"+r"(d[1]),"+r"(d[2]),"+r"(d[3])
        : "r"(a[0]),"r"(a[1]),"r"(a[2]),"r"(a[3]),"r"(b[0]),"r"(b[1]));
}

// ---------------- merged prep ----------------
__global__ void prep_all(const float* qw, const float* kw, const float* vw,
                         const float* ow, const float* up, const float* dn,
                         const float* tok_emb, const float* attn_nw,
                         const float* ff_nw, const float* fin_nw){
    int m = blockIdx.x;
    if(m < 24){
        const float* src; int8_t* dst; int n;
        if(m < 16){
            int l = m >> 2, wsel = m & 3; n = D*D;
            const float* bases[4] = {qw,kw,vw,ow};
            int8_t* dsts[4] = {g_wq,g_wk,g_wv,g_wo};
            src = bases[wsel] + l*n; dst = dsts[wsel] + l*n;
        } else if(m < 20){ int l=m-16; n=DFF*D; src=up+l*n; dst=g_wup+l*n; }
        else             { int l=m-20; n=D*DFF; src=dn+l*n; dst=g_wdn+l*n; }

        __shared__ float red[256];
        float s = 0.f;
        for(int i=threadIdx.x;i<n;i+=256) s += fabsf(src[i]);
        red[threadIdx.x]=s; __syncthreads();
        for(int o=128;o>0;o>>=1){ if(threadIdx.x<o) red[threadIdx.x]+=red[threadIdx.x+o]; __syncthreads(); }
        float scale = fmaxf(__fdiv_rn(red[0], (float)n), 1e-5f);
        for(int i=threadIdx.x;i<n;i+=256){
            float t = rintf(__fdiv_rn(src[i], scale));
            t = fminf(fmaxf(t,-1.f),1.f);
            dst[i] = (int8_t)(int)t;
        }
        return;
    }
    int i = (m-24)*256 + threadIdx.x;
    if(i < VOCAB*D){
        float r = rintf(__fmul_rn(tok_emb[i],1024.f));
        int q = clampi((int)r,-32768,32767);
        g_ehi[i] = (int8_t)(q >> 8);
        g_elo[i] = (uint8_t)(q & 0xff);
    }
    if(m == 24){
        int t=threadIdx.x;
        for(int j=t;j<NL*D;j+=256){
            g_gattn[j] = gammaq(attn_nw[j]);
            g_gff[j]   = gammaq(ff_nw[j]);
        }
        if(t<D) g_gfin[t] = gammaq(fin_nw[t]);
    }
}

// ---------------- token+pos embedding ----------------
__global__ void embed_kernel(const int* tokens, const float* tok_emb, const float* pos_emb){
    int i = blockIdx.x*256 + threadIdx.x;
    if(i >= BT*D) return;
    int bt = i >> 6, d = i & 63;
    int t = bt & (T-1);
    int tok = tokens[bt];
    int tq = clampi((int)rintf(__fmul_rn(tok_emb[tok*D+d],1024.f)),-32768,32767);
    int pq = clampi((int)rintf(__fmul_rn(pos_emb[t*D+d],1024.f)),-32768,32767);
    g_x[i] = (int8_t)wrap8((tq+pq) >> 3);
}

// ---------------- final rmsnorm ----------------
__global__ void rmsnorm_final_kernel(){
    int row  = (blockIdx.x*blockDim.x + threadIdx.x) >> 5;
    int lane = threadIdx.x & 31;
    if(row >= BT) return;
    const int8_t* r = g_x + row*D;
    int x0 = r[lane*2], x1 = r[lane*2+1];
    int y0,y1;
    rms_pair(x0,x1,g_gfin[lane*2],g_gfin[lane*2+1],y0,y1);
    g_h[row*D+lane*2]   = (int8_t)y0;
    g_h[row*D+lane*2+1] = (int8_t)y1;
}

// ---------------- fused rmsnorm + QKV via MMA (V written transposed) ----------------
__global__ __launch_bounds__(256) void qkv_norm_kernel(int layer){
    __shared__ uint8_t shb[16*68];
    int tid = threadIdx.x, warp = tid>>5, lane = tid&31;
    int g = lane>>2, tg = lane&3;
    int bt0 = blockIdx.x*16;
    const int* gm = g_gattn + layer*D;
    #pragma unroll
    for(int t=0;t<2;t++){
        int tok = 2*warp + t;
        const int8_t* xr = g_x + (bt0+tok)*D;
        int x0 = xr[2*lane], x1 = xr[2*lane+1];
        int y0,y1;
        rms_pair(x0,x1,gm[2*lane],gm[2*lane+1],y0,y1);
        shb[tok*68 + 2*lane]   = (uint8_t)(y0 & 0xff);
        shb[tok*68 + 2*lane+1] = (uint8_t)(y1 & 0xff);
    }
    __syncthreads();
    const int* shi = (const int*)shb;
    int a[2][4];
    #pragma unroll
    for(int kc=0;kc<2;kc++){
        a[kc][0] = shi[g*17     + kc*8 + tg];
        a[kc][1] = shi[(g+8)*17 + kc*8 + tg];
        a[kc][2] = shi[g*17     + kc*8 + 4 + tg];
        a[kc][3] = shi[(g+8)*17 + kc*8 + 4 + tg];
    }
    const int* wq = (const int*)(g_wq + layer*D*D);
    const int* wk = (const int*)(g_wk + layer*D*D);
    const int* wv = (const int*)(g_wv + layer*D*D);
    #pragma unroll
    for(int nt=0;nt<3;nt++){
        const int* wb = (nt==0) ? wq : (nt==1 ? wk : wv);
        int c = warp*8 + g;
        int d[4] = {0,0,0,0};
        #pragma unroll
        for(int kc=0;kc<2;kc++){
            int b[2] = { wb[c*16 + kc*8 + tg], wb[c*16 + kc*8 + 4 + tg] };
            mma_s8s8(d, a[kc], b);
        }
        int o0 = warp*8 + 2*tg;
        int v0 = clampi(d[0]>>6,-128,127), v1 = clampi(d[1]>>6,-128,127);
        int v2 = clampi(d[2]>>6,-128,127), v3 = clampi(d[3]>>6,-128,127);
        if(nt < 2){
            int8_t* dst = (nt==0) ? g_q : g_k;
            *(uint16_t*)(dst + (bt0+g)*64   + o0) = (uint16_t)((v0&0xff) | ((v1&0xff)<<8));
            *(uint16_t*)(dst + (bt0+g+8)*64 + o0) = (uint16_t)((v2&0xff) | ((v3&0xff)<<8));
        } else {
            // V -> transposed quad-packed layout
            int bt_a = bt0 + g, bt_b = bt0 + g + 8;
            int bsel = bt_a >> 10;
            int ta = bt_a & (T-1), tb = bt_b & (T-1);
            int hh = o0 >> 5, hd = o0 & 31;
            int8_t* vtb = g_vt + (bsel*2 + hh)*((T/4)*HD*4);
            vtb[(ta>>2)*128 + hd*4     + (ta&3)] = (int8_t)v0;
            vtb[(ta>>2)*128 + (hd+1)*4 + (ta&3)] = (int8_t)v1;
            vtb[(tb>>2)*128 + hd*4     + (tb&3)] = (int8_t)v2;
            vtb[(tb>>2)*128 + (hd+1)*4 + (tb&3)] = (int8_t)v3;
        }
    }
}

// ---------------- fused attention: scores + LUT softmax + MMA AV (V^T from global) ----------------
#define SK_WORDS   (T*8)
#define SP_PITCH   1040
#define SP_BYTES   (8*SP_PITCH)
#define ATTN_SMEM  (SK_WORDS*4 + SP_BYTES + 256*4)
__device__ __forceinline__ int ksw(int k,int w){ return k*8 + (w ^ ((k>>2)&7)); }

__global__ __launch_bounds__(256) void attn_fused_kernel(){
    extern __shared__ unsigned dyn[];
    unsigned* sK  = dyn;
    uint8_t*  sP  = (uint8_t*)(dyn + SK_WORDS);
    int*      sred = (int*)(sP + SP_BYTES);
    int bh = blockIdx.y; int b = bh>>1, h = bh&1;
    int warp = threadIdx.x>>5, lane = threadIdx.x&31;
    int g = lane>>2, tg = lane&3;

    int jmaxb = (blockIdx.x*8+7)>>5;
    int KN = (jmaxb+1)*32;

    const unsigned* kb = (const unsigned*)g_k + (b*T)*16 + h*8;
    for(int idx=threadIdx.x; idx<KN*8; idx+=256){
        int k = idx>>3, w = idx&7;
        sK[ksw(k,w)] = kb[k*16+w];
    }
    __syncthreads();

    int q = blockIdx.x*8 + warp;
    const unsigned* qv = (const unsigned*)g_q + (b*T+q)*16 + h*8;
    unsigned qr[8];
    #pragma unroll
    for(int w=0;w<8;w++) qr[w] = qv[w];

    const int NEG = (int)0x80000000;
    int sc[32];
    int mx = NEG;
    #pragma unroll
    for(int j=0;j<32;j++){
        sc[j] = NEG;
        if(j > jmaxb) break;
        int k = j*32 + lane;
        if(k <= q){
            int acc = 0;
            #pragma unroll
            for(int w=0;w<8;w++) acc = __dp4a((int)qr[w], (int)sK[ksw(k,w)], acc);
            float p = __int2float_rn(acc*45);
            int s = (int)floorf(__fmul_rn(p, 0.00390625f));
            sc[j] = s; mx = max(mx, s);
        }
    }
    #pragma unroll
    for(int o=16;o>0;o>>=1) mx = max(mx, __shfl_xor_sync(0xffffffffu, mx, o));

    int sh_l = lane - 24;
    int ea_l = (sh_l>=-3) ? 256 + sh_l*64
             : (sh_l>=-8) ? 64 + (sh_l+3)*11
             : sh_l + 24;
    if(lane > 24) ea_l = 0;

    int su = 0;
    #pragma unroll
    for(int j=0;j<32;j++){
        if(j > jmaxb) break;
        bool valid = (sc[j] != NEG);
        int idx = valid ? (sc[j] - mx + 24) : -1;
        int idxc = clampi(idx, 0, 31);
        int ea = __shfl_sync(0xffffffffu, ea_l, idxc);
        if(!(valid && idx >= 0)) ea = 0;
        su += ea;
        sc[j] = (valid && idx >= 0) ? idx : 32;
    }
    #pragma unroll
    for(int o=16;o>0;o>>=1) su += __shfl_xor_sync(0xffffffffu, su, o);
    float sf = (float)max(su, 1);

    int p_l = 0;
    if(ea_l > 0)
        p_l = clampi((int)rintf(__fmul_rn(__fdiv_rn((float)ea_l, sf), 255.f)), 0, 255);

    uint8_t* prow = sP + warp*SP_PITCH;
    #pragma unroll
    for(int j=0;j<32;j++){
        if(j > jmaxb) break;
        int idx = sc[j];
        int p = __shfl_sync(0xffffffffu, p_l, idx & 31);
        if(idx >= 32) p = 0;
        prow[j*32+lane] = (uint8_t)p;
    }
    __syncthreads();

    // AV via u8 x s8 MMA, V^T fragments straight from global
    int nt = warp & 3, half = warp >> 2;
    int dim = nt*8 + g;
    const int* vt = (const int*)(g_vt) + bh*((T/4)*HD);
    int dacc[4] = {0,0,0,0};
    for(int c32 = half; c32 <= jmaxb; c32 += 2){
        const uint8_t* pr = sP + g*SP_PITCH + c32*32;
        unsigned A[4];
        A[0] = *(const unsigned*)(pr + tg*4);
        A[1] = A[0];
        A[2] = *(const unsigned*)(pr + 16 + tg*4);
        A[3] = A[2];
        int Bv[2];
        Bv[0] = vt[(c32*8 + tg)*32 + dim];
        Bv[1] = vt[(c32*8 + 4 + tg)*32 + dim];
        mma_u8s8(dacc, A, Bv);
    }
    if(half == 1){
        sred[nt*64 + g*8 + 2*tg]     = dacc[0];
        sred[nt*64 + g*8 + 2*tg + 1] = dacc[1];
    }
    __syncthreads();
    if(half == 0){
        int v0 = dacc[0] + sred[nt*64 + g*8 + 2*tg];
        int v1 = dacc[1] + sred[nt*64 + g*8 + 2*tg + 1];
        int qq = blockIdx.x*8 + g;
        int o0 = wrap8(v0>>8) & 0xff, o1 = wrap8(v1>>8) & 0xff;
        *(uint16_t*)(g_a + (b*T+qq)*64 + h*32 + nt*8 + 2*tg) = (uint16_t)(o0 | (o1<<8));
    }
}

// ---------------- fused oproj+residual+rmsnorm+FFN+residual via MMA ----------------
__global__ __launch_bounds__(256) void ffn_fused_kernel(int layer){
    __shared__ int      sa[16*17];
    __shared__ uint8_t  sxb[16*64];
    __shared__ uint8_t  shb[16*68];
    __shared__ uint8_t  sub[16*260];
    int tid = threadIdx.x, warp = tid>>5, lane = tid&31;
    int g = lane>>2, tg = lane&3;
    int bt0 = blockIdx.x*16;

    {
        int tok = tid>>4, i = tid&15;
        sa[tok*17+i] = ((const int*)g_a)[(bt0+tok)*16 + i];
    }
    __syncthreads();

    {   // oproj
        int a[2][4];
        #pragma unroll
        for(int kc=0;kc<2;kc++){
            a[kc][0] = sa[g*17     + kc*8 + tg];
            a[kc][1] = sa[(g+8)*17 + kc*8 + tg];
            a[kc][2] = sa[g*17     + kc*8 + 4 + tg];
            a[kc][3] = sa[(g+8)*17 + kc*8 + 4 + tg];
        }
        const int* wo = (const int*)(g_wo + layer*D*D);
        int c = warp*8 + g;
        int d[4] = {0,0,0,0};
        #pragma unroll
        for(int kc=0;kc<2;kc++){
            int b[2] = { wo[c*16 + kc*8 + tg], wo[c*16 + kc*8 + 4 + tg] };
            mma_s8s8(d, a[kc], b);
        }
        int o0 = warp*8 + 2*tg;
        int r0 = clampi(d[0]>>6,-128,127), r1 = clampi(d[1]>>6,-128,127);
        int r2 = clampi(d[2]>>6,-128,127), r3 = clampi(d[3]>>6,-128,127);
        sxb[g*64 + o0]       = (uint8_t)(wrap8((int)g_x[(bt0+g)*64 + o0]     + r0) & 0xff);
        sxb[g*64 + o0+1]     = (uint8_t)(wrap8((int)g_x[(bt0+g)*64 + o0+1]   + r1) & 0xff);
        sxb[(g+8)*64 + o0]   = (uint8_t)(wrap8((int)g_x[(bt0+g+8)*64 + o0]   + r2) & 0xff);
        sxb[(g+8)*64 + o0+1] = (uint8_t)(wrap8((int)g_x[(bt0+g+8)*64 + o0+1] + r3) & 0xff);
    }
    __syncthreads();

    {   // rmsnorm
        const int* gm = g_gff + layer*D;
        #pragma unroll
        for(int t=0;t<2;t++){
            int tok = 2*warp + t;
            int x0 = (int)(int8_t)sxb[tok*64 + 2*lane];
            int x1 = (int)(int8_t)sxb[tok*64 + 2*lane+1];
            int y0,y1;
            rms_pair(x0,x1,gm[2*lane],gm[2*lane+1],y0,y1);
            shb[tok*68 + 2*lane]   = (uint8_t)(y0 & 0xff);
            shb[tok*68 + 2*lane+1] = (uint8_t)(y1 & 0xff);
        }
    }
    __syncthreads();

    {   // up + relu
        const int* shi = (const int*)shb;
        int a[2][4];
        #pragma unroll
        for(int kc=0;kc<2;kc++){
            a[kc][0] = shi[g*17     + kc*8 + tg];
            a[kc][1] = shi[(g+8)*17 + kc*8 + tg];
            a[kc][2] = shi[g*17     + kc*8 + 4 + tg];
            a[kc][3] = shi[(g+8)*17 + kc*8 + 4 + tg];
        }
        const int* wu = (const int*)(g_wup + layer*DFF*D);
        #pragma unroll
        for(int nt=0;nt<4;nt++){
            int colb = warp*32 + nt*8;
            int c = colb + g;
            int d[4] = {0,0,0,0};
            #pragma unroll
            for(int kc=0;kc<2;kc++){
                int b[2] = { wu[c*16 + kc*8 + tg], wu[c*16 + kc*8 + 4 + tg] };
                mma_s8s8(d, a[kc], b);
            }
            int c0 = colb + 2*tg;
            int u0 = max(clampi(d[0]>>6,-128,127),0), u1 = max(clampi(d[1]>>6,-128,127),0);
            int u2 = max(clampi(d[2]>>6,-128,127),0), u3 = max(clampi(d[3]>>6,-128,127),0);
            sub[g*260 + c0]       = (uint8_t)u0;
            sub[g*260 + c0+1]     = (uint8_t)u1;
            sub[(g+8)*260 + c0]   = (uint8_t)u2;
            sub[(g+8)*260 + c0+1] = (uint8_t)u3;
        }
    }
    __syncthreads();

    {   // down (K=256)
        const int* sui = (const int*)sub;
        const int* wd = (const int*)(g_wdn + layer*D*DFF);
        int c = warp*8 + g;
        int d[4] = {0,0,0,0};
        #pragma unroll
        for(int kc=0;kc<8;kc++){
            int a[4];
            a[0] = sui[g*65     + kc*8 + tg];
            a[1] = sui[(g+8)*65 + kc*8 + tg];
            a[2] = sui[g*65     + kc*8 + 4 + tg];
            a[3] = sui[(g+8)*65 + kc*8 + 4 + tg];
            int b[2] = { wd[c*64 + kc*8 + tg], wd[c*64 + kc*8 + 4 + tg] };
            mma_s8s8(d, a, b);
        }
        int o0 = warp*8 + 2*tg;
        int r0 = clampi(d[0]>>6,-128,127), r1 = clampi(d[1]>>6,-128,127);
        int r2 = clampi(d[2]>>6,-128,127), r3 = clampi(d[3]>>6,-128,127);
        g_x[(bt0+g)*64 + o0]     = (int8_t)wrap8((int)(int8_t)sxb[g*64 + o0]       + r0);
        g_x[(bt0+g)*64 + o0+1]   = (int8_t)wrap8((int)(int8_t)sxb[g*64 + o0+1]     + r1);
        g_x[(bt0+g+8)*64 + o0]   = (int8_t)wrap8((int)(int8_t)sxb[(g+8)*64 + o0]   + r2);
        g_x[(bt0+g+8)*64 + o0+1] = (int8_t)wrap8((int)(int8_t)sxb[(g+8)*64 + o0+1] + r3);
    }
}

// ---------------- logits via IMMA ----------------
__global__ __launch_bounds__(256) void logits_mma_kernel(float* __restrict__ out){
    int warp = threadIdx.x>>5, lane = threadIdx.x&31;
    int g = lane>>2, tg = lane&3;
    int vbase = blockIdx.x*256 + warp*32;
    int mbase = blockIdx.y*64;

    int bhi[4][2][2], blo[4][2][2];
    #pragma unroll
    for(int nt=0;nt<4;nt++){
        int col = vbase + nt*8 + g;
        const int8_t*  eh = g_ehi + col*64;
        const uint8_t* el = g_elo + col*64;
        #pragma unroll
        for(int kc=0;kc<2;kc++){
            bhi[nt][kc][0] = *(const int*)(eh + kc*32 + tg*4);
            bhi[nt][kc][1] = *(const int*)(eh + kc*32 + 16 + tg*4);
            blo[nt][kc][0] = *(const int*)(el + kc*32 + tg*4);
            blo[nt][kc][1] = *(const int*)(el + kc*32 + 16 + tg*4);
        }
    }
    #pragma unroll
    for(int mt=0;mt<4;mt++){
        int row0 = mbase + mt*16 + g;
        const int8_t* h0 = g_h + row0*64;
        const int8_t* h8 = g_h + (row0+8)*64;
        int a[2][4];
        #pragma unroll
        for(int kc=0;kc<2;kc++){
            a[kc][0] = *(const int*)(h0 + kc*32 + tg*4);
            a[kc][1] = *(const int*)(h8 + kc*32 + tg*4);
            a[kc][2] = *(const int*)(h0 + kc*32 + 16 + tg*4);
            a[kc][3] = *(const int*)(h8 + kc*32 + 16 + tg*4);
        }
        #pragma unroll
        for(int nt=0;nt<4;nt++){
            int dh[4]={0,0,0,0}, dl[4]={0,0,0,0};
            #pragma unroll
            for(int kc=0;kc<2;kc++){
                mma_s8s8(dh, a[kc], bhi[nt][kc]);
                mma_s8u8(dl, a[kc], blo[nt][kc]);
            }
            int col = vbase + nt*8 + 2*tg;
            float2 v0, v1;
            v0.x = __fmul_rn((float)(dh[0]*256+dl[0]), 1.220703125e-4f);
            v0.y = __fmul_rn((float)(dh[1]*256+dl[1]), 1.220703125e-4f);
            v1.x = __fmul_rn((float)(dh[2]*256+dl[2]), 1.220703125e-4f);
            v1.y = __fmul_rn((float)(dh[3]*256+dl[3]), 1.220703125e-4f);
            *(float2*)(out + (size_t)row0*VOCAB + col)     = v0;
            *(float2*)(out + (size_t)(row0+8)*VOCAB + col) = v1;
        }
    }
}

// ---------------- launch ----------------
extern "C" void kernel_launch(void* const* d_in, const int* in_sizes, int n_in,
                              void* d_out, int out_size){
    const int*   tokens  = (const int*)  d_in[0];
    const float* tok_emb = (const float*)d_in[1];
    const float* pos_emb = (const float*)d_in[2];
    const float* attn_nw = (const float*)d_in[3];
    const float* qw      = (const float*)d_in[4];
    const float* kw      = (const float*)d_in[5];
    const float* vw      = (const float*)d_in[6];
    const float* ow      = (const float*)d_in[7];
    const float* ff_nw   = (const float*)d_in[8];
    const float* up      = (const float*)d_in[9];
    const float* dn      = (const float*)d_in[10];
    const float* fin_nw  = (const float*)d_in[11];
    float* out = (float*)d_out;

    cudaFuncSetAttribute(attn_fused_kernel,
                         cudaFuncAttributeMaxDynamicSharedMemorySize, ATTN_SMEM);

    prep_all<<<24 + (VOCAB*D+255)/256, 256>>>(qw,kw,vw,ow,up,dn,
                                              tok_emb, attn_nw, ff_nw, fin_nw);
    embed_kernel<<<(BT*D+255)/256,256>>>(tokens, tok_emb, pos_emb);

    for(int l=0;l<NL;l++){
        qkv_norm_kernel<<<BT/16,256>>>(l);
        attn_fused_kernel<<<dim3(T/8, BATCH*H),256,ATTN_SMEM>>>();
        ffn_fused_kernel<<<BT/16,256>>>(l);
    }
    rmsnorm_final_kernel<<<BT/8,256>>>();
    logits_mma_kernel<<<dim3(VOCAB/256, BT/64),256>>>(out);
}

// round 10
// speedup vs baseline: 1.0812x; 1.0104x over previous
#include <cuda_runtime.h>
#include <cstdint>
#include <climits>

#define BATCH 4
#define T 1024
#define D 64
#define H 2
#define HD 32
#define DFF 256
#define NL 4
#define VOCAB 8192
#define BT (BATCH*T)

// ---------------- device scratch (no allocs allowed) ----------------
__device__ __align__(16) int8_t  g_x[BT*D];
__device__ __align__(16) int8_t  g_h[BT*D];
__device__ __align__(16) int8_t  g_q[BT*D];
__device__ __align__(16) int8_t  g_k[BT*D];
__device__ __align__(16) int8_t  g_a[BT*D];
__device__ __align__(16) int8_t  g_vt[BATCH*H*(T/4)*HD*4];  // V transposed quad-packed
__device__ __align__(16) int8_t  g_wq[NL*D*D], g_wk[NL*D*D], g_wv[NL*D*D], g_wo[NL*D*D];
__device__ __align__(16) int8_t  g_wup[NL*DFF*D], g_wdn[NL*D*DFF];
__device__ __align__(16) int     g_gattn[NL*D], g_gff[NL*D], g_gfin[D];
__device__ __align__(16) int8_t  g_ehi[VOCAB*D];
__device__ __align__(16) uint8_t g_elo[VOCAB*D];

// ---------------- helpers ----------------
__device__ __forceinline__ int wrap8(int v){ return (int)(signed char)(v & 0xff); }
__device__ __forceinline__ int clampi(int v,int lo,int hi){ return min(max(v,lo),hi); }
__device__ __forceinline__ int gammaq(float w){
    float c = fminf(fmaxf(w,-2.f),2.f);
    float r = rintf(__fmul_rn(c,1024.f));
    return clampi((int)r,-32768,32767);
}
__device__ __forceinline__ void rms_pair(int x0,int x1,int g0,int g1,int& y0,int& y1){
    int ss = x0*x0 + x1*x1;
    #pragma unroll
    for(int o=16;o>0;o>>=1) ss += __shfl_xor_sync(0xffffffffu, ss, o);
    int mean_sq = ss >> 6;
    int lut = min(mean_sq >> 6, 255);
    float bc = (float)(lut*64 + 32);
    int inv = clampi((int)rintf(__fdiv_rn(16384.f, __fsqrt_rn(bc))), 0, 16383);
    int p0 = (x0*inv) >> 8, p1 = (x1*inv) >> 8;
    y0 = clampi((int)floorf(__fmul_rn(__fmul_rn((float)p0,(float)g0), 0.0009765625f)),-128,127);
    y1 = clampi((int)floorf(__fmul_rn(__fmul_rn((float)p1,(float)g1), 0.0009765625f)),-128,127);
}
// m16n8k32 int8 MMA
__device__ __forceinline__ void mma_s8s8(int* d, const int* a, const int* b){
    asm("mma.sync.aligned.m16n8k32.row.col.s32.s8.s8.s32 "
        "{%0,%1,%2,%3},{%4,%5,%6,%7},{%8,%9},{%0,%1,%2,%3};"
        : "+r"(d[0]),"+r"(d[1]),"+r"(d[2]),"+r"(d[3])
        : "r"(a[0]),"r"(a[1]),"r"(a[2]),"r"(a[3]),"r"(b[0]),"r"(b[1]));
}
__device__ __forceinline__ void mma_s8u8(int* d, const int* a, const int* b){
    asm("mma.sync.aligned.m16n8k32.row.col.s32.s8.u8.s32 "
        "{%0,%1,%2,%3},{%4,%5,%6,%7},{%8,%9},{%0,%1,%2,%3};"
        : "+r"(d[0]),"+r"(d[1]),"+r"(d[2]),"+r"(d[3])
        : "r"(a[0]),"r"(a[1]),"r"(a[2]),"r"(a[3]),"r"(b[0]),"r"(b[1]));
}
__device__ __forceinline__ void mma_u8s8(int* d, const unsigned* a, const int* b){
    asm("mma.sync.aligned.m16n8k32.row.col.s32.u8.s8.s32 "
        "{%0,%1,%2,%3},{%4,%5,%6,%7},{%8,%9},{%0,%1,%2,%3};"
        : "+r"(d[0]),"+r"(d[1]),"+r"(d[2]),"+r"(d[3])
        : "r"(a[0]),"r"(a[1]),"r"(a[2]),"r"(a[3]),"r"(b[0]),"r"(b[1]));
}
__device__ __forceinline__ int ea_of_idx(int l){
    return (l<16) ? l : (l<21 ? 64+11*(l-21) : (l<=24 ? 256+64*(l-24) : 0));
}

// ---------------- merged prep ----------------
__global__ void prep_all(const float* qw, const float* kw, const float* vw,
                         const float* ow, const float* up, const float* dn,
                         const float* tok_emb, const float* attn_nw,
                         const float* ff_nw, const float* fin_nw){
    int m = blockIdx.x;
    if(m < 24){
        const float* src; int8_t* dst; int n;
        if(m < 16){
            int l = m >> 2, wsel = m & 3; n = D*D;
            const float* bases[4] = {qw,kw,vw,ow};
            int8_t* dsts[4] = {g_wq,g_wk,g_wv,g_wo};
            src = bases[wsel] + l*n; dst = dsts[wsel] + l*n;
        } else if(m < 20){ int l=m-16; n=DFF*D; src=up+l*n; dst=g_wup+l*n; }
        else             { int l=m-20; n=D*DFF; src=dn+l*n; dst=g_wdn+l*n; }

        __shared__ float red[256];
        float s = 0.f;
        for(int i=threadIdx.x;i<n;i+=256) s += fabsf(src[i]);
        red[threadIdx.x]=s; __syncthreads();
        for(int o=128;o>0;o>>=1){ if(threadIdx.x<o) red[threadIdx.x]+=red[threadIdx.x+o]; __syncthreads(); }
        float scale = fmaxf(__fdiv_rn(red[0], (float)n), 1e-5f);
        for(int i=threadIdx.x;i<n;i+=256){
            float t = rintf(__fdiv_rn(src[i], scale));
            t = fminf(fmaxf(t,-1.f),1.f);
            dst[i] = (int8_t)(int)t;
        }
        return;
    }
    int i = (m-24)*256 + threadIdx.x;
    if(i < VOCAB*D){
        float r = rintf(__fmul_rn(tok_emb[i],1024.f));
        int q = clampi((int)r,-32768,32767);
        g_ehi[i] = (int8_t)(q >> 8);
        g_elo[i] = (uint8_t)(q & 0xff);
    }
    if(m == 24){
        int t=threadIdx.x;
        for(int j=t;j<NL*D;j+=256){
            g_gattn[j] = gammaq(attn_nw[j]);
            g_gff[j]   = gammaq(ff_nw[j]);
        }
        if(t<D) g_gfin[t] = gammaq(fin_nw[t]);
    }
}

// ---------------- token+pos embedding ----------------
__global__ void embed_kernel(const int* tokens, const float* tok_emb, const float* pos_emb){
    int i = blockIdx.x*256 + threadIdx.x;
    if(i >= BT*D) return;
    int bt = i >> 6, d = i & 63;
    int t = bt & (T-1);
    int tok = tokens[bt];
    int tq = clampi((int)rintf(__fmul_rn(tok_emb[tok*D+d],1024.f)),-32768,32767);
    int pq = clampi((int)rintf(__fmul_rn(pos_emb[t*D+d],1024.f)),-32768,32767);
    g_x[i] = (int8_t)wrap8((tq+pq) >> 3);
}

// ---------------- final rmsnorm ----------------
__global__ void rmsnorm_final_kernel(){
    int row  = (blockIdx.x*blockDim.x + threadIdx.x) >> 5;
    int lane = threadIdx.x & 31;
    if(row >= BT) return;
    const int8_t* r = g_x + row*D;
    int x0 = r[lane*2], x1 = r[lane*2+1];
    int y0,y1;
    rms_pair(x0,x1,g_gfin[lane*2],g_gfin[lane*2+1],y0,y1);
    g_h[row*D+lane*2]   = (int8_t)y0;
    g_h[row*D+lane*2+1] = (int8_t)y1;
}

// ---------------- fused rmsnorm + QKV via MMA (V written transposed) ----------------
__global__ __launch_bounds__(256) void qkv_norm_kernel(int layer){
    __shared__ uint8_t shb[16*68];
    int tid = threadIdx.x, warp = tid>>5, lane = tid&31;
    int g = lane>>2, tg = lane&3;
    int bt0 = blockIdx.x*16;
    const int* gm = g_gattn + layer*D;
    #pragma unroll
    for(int t=0;t<2;t++){
        int tok = 2*warp + t;
        const int8_t* xr = g_x + (bt0+tok)*D;
        int x0 = xr[2*lane], x1 = xr[2*lane+1];
        int y0,y1;
        rms_pair(x0,x1,gm[2*lane],gm[2*lane+1],y0,y1);
        shb[tok*68 + 2*lane]   = (uint8_t)(y0 & 0xff);
        shb[tok*68 + 2*lane+1] = (uint8_t)(y1 & 0xff);
    }
    __syncthreads();
    const int* shi = (const int*)shb;
    int a[2][4];
    #pragma unroll
    for(int kc=0;kc<2;kc++){
        a[kc][0] = shi[g*17     + kc*8 + tg];
        a[kc][1] = shi[(g+8)*17 + kc*8 + tg];
        a[kc][2] = shi[g*17     + kc*8 + 4 + tg];
        a[kc][3] = shi[(g+8)*17 + kc*8 + 4 + tg];
    }
    const int* wq = (const int*)(g_wq + layer*D*D);
    const int* wk = (const int*)(g_wk + layer*D*D);
    const int* wv = (const int*)(g_wv + layer*D*D);
    #pragma unroll
    for(int nt=0;nt<3;nt++){
        const int* wb = (nt==0) ? wq : (nt==1 ? wk : wv);
        int c = warp*8 + g;
        int d[4] = {0,0,0,0};
        #pragma unroll
        for(int kc=0;kc<2;kc++){
            int b[2] = { wb[c*16 + kc*8 + tg], wb[c*16 + kc*8 + 4 + tg] };
            mma_s8s8(d, a[kc], b);
        }
        int o0 = warp*8 + 2*tg;
        int v0 = clampi(d[0]>>6,-128,127), v1 = clampi(d[1]>>6,-128,127);
        int v2 = clampi(d[2]>>6,-128,127), v3 = clampi(d[3]>>6,-128,127);
        if(nt < 2){
            int8_t* dst = (nt==0) ? g_q : g_k;
            *(uint16_t*)(dst + (bt0+g)*64   + o0) = (uint16_t)((v0&0xff) | ((v1&0xff)<<8));
            *(uint16_t*)(dst + (bt0+g+8)*64 + o0) = (uint16_t)((v2&0xff) | ((v3&0xff)<<8));
        } else {
            int bt_a = bt0 + g, bt_b = bt0 + g + 8;
            int bsel = bt_a >> 10;
            int ta = bt_a & (T-1), tb = bt_b & (T-1);
            int hh = o0 >> 5, hd = o0 & 31;
            int8_t* vtb = g_vt + (bsel*2 + hh)*((T/4)*HD*4);
            vtb[(ta>>2)*128 + hd*4     + (ta&3)] = (int8_t)v0;
            vtb[(ta>>2)*128 + (hd+1)*4 + (ta&3)] = (int8_t)v1;
            vtb[(tb>>2)*128 + hd*4     + (tb&3)] = (int8_t)v2;
            vtb[(tb>>2)*128 + (hd+1)*4 + (tb&3)] = (int8_t)v3;
        }
    }
}

// ---------------- attention: full MMA scores + LUT softmax + MMA AV ----------------
#define SC_PITCH  1028                       // ints per score row
#define SPB_PITCH 1040                       // bytes per prob row
#define ATTN_SMEM (16*SC_PITCH*4 + 16*SPB_PITCH + 512 + 128 + 16*36*4)

__global__ __launch_bounds__(256) void attn_fused_kernel(){
    extern __shared__ int smem_i[];
    int*      sS   = smem_i;                                  // scores 16 x 1028
    uint8_t*  sP   = (uint8_t*)(smem_i + 16*SC_PITCH);        // probs 16 x 1040
    uint8_t*  plut = sP + 16*SPB_PITCH;                       // 16 x 32
    int*      rowmax = (int*)(plut + 512);
    int*      rowsum = rowmax + 16;
    int*      sred   = rowsum + 16;                           // 16 x 36

    int tid = threadIdx.x, warp = tid>>5, lane = tid&31;
    int g = lane>>2, tg = lane&3;
    int qt = blockIdx.x, bh = blockIdx.y, b = bh>>1, h = bh&1;
    int qb = qt*16, base = b*T;
    int KN = qb + 16, nch = KN >> 3;
    int KNpad = (KN + 31) & ~31;

    if(tid < 16){ rowmax[tid] = INT_MIN; rowsum[tid] = 0; }
    __syncthreads();

    // ---- score pass (MMA, no staging) ----
    const int* qp = (const int*)g_q;
    int aq[4];
    aq[0] = qp[(base+qb+g)*16   + h*8 + tg];
    aq[1] = qp[(base+qb+g+8)*16 + h*8 + tg];
    aq[2] = qp[(base+qb+g)*16   + h*8 + 4 + tg];
    aq[3] = qp[(base+qb+g+8)*16 + h*8 + 4 + tg];
    const int* kp = (const int*)g_k;
    int r0 = qb + g, r8 = qb + g + 8;
    int mg = INT_MIN, mg8 = INT_MIN;
    for(int c = warp; c < nch; c += 8){
        int k0 = c*8;
        int bv[2];
        bv[0] = kp[(base+k0+g)*16 + h*8 + tg];
        bv[1] = kp[(base+k0+g)*16 + h*8 + 4 + tg];
        int d[4] = {0,0,0,0};
        mma_s8s8(d, aq, bv);
        int c0 = k0 + 2*tg;
        int s0 = (int)floorf(__fmul_rn(__int2float_rn(d[0]*45), 0.00390625f));
        int s1 = (int)floorf(__fmul_rn(__int2float_rn(d[1]*45), 0.00390625f));
        int s2 = (int)floorf(__fmul_rn(__int2float_rn(d[2]*45), 0.00390625f));
        int s3 = (int)floorf(__fmul_rn(__int2float_rn(d[3]*45), 0.00390625f));
        if(c0   > r0) s0 = -32767;
        if(c0+1 > r0) s1 = -32767;
        if(c0   > r8) s2 = -32767;
        if(c0+1 > r8) s3 = -32767;
        sS[g*SC_PITCH + c0]     = s0;
        sS[g*SC_PITCH + c0+1]   = s1;
        sS[(g+8)*SC_PITCH + c0]   = s2;
        sS[(g+8)*SC_PITCH + c0+1] = s3;
        mg  = max(mg,  max(s0,s1));
        mg8 = max(mg8, max(s2,s3));
    }
    mg  = max(mg,  __shfl_xor_sync(0xffffffffu, mg , 1));
    mg  = max(mg,  __shfl_xor_sync(0xffffffffu, mg , 2));
    mg8 = max(mg8, __shfl_xor_sync(0xffffffffu, mg8, 1));
    mg8 = max(mg8, __shfl_xor_sync(0xffffffffu, mg8, 2));
    if(tg == 0){
        atomicMax(&rowmax[g],   mg);
        atomicMax(&rowmax[g+8], mg8);
    }
    __syncthreads();

    // ---- idx + ea-sum pass: warp handles rows 2w, 2w+1 ----
    int ea_l = ea_of_idx(lane);
    #pragma unroll
    for(int rr = 0; rr < 2; rr++){
        int r = 2*warp + rr;
        int m = rowmax[r];
        int su = 0;
        for(int col = lane; col < KNpad; col += 32){
            int s = (col < KN) ? sS[r*SC_PITCH + col] : -32767;
            int idx = min(max(s - m + 24, 0), 24);
            su += __shfl_sync(0xffffffffu, ea_l, idx);
            sP[r*SPB_PITCH + col] = (uint8_t)idx;
        }
        #pragma unroll
        for(int o=16;o>0;o>>=1) su += __shfl_xor_sync(0xffffffffu, su, o);
        if(lane == 0) rowsum[r] = su;
    }
    __syncthreads();

    // ---- per-row prob LUT (exact fdiv chain, 25 entries/row) ----
    for(int e = tid; e < 512; e += 256){
        int row = e>>5, l = e&31;
        int p = 0;
        if(l <= 24){
            int ea = ea_of_idx(l);
            if(ea > 0){
                float sf = (float)max(rowsum[row], 1);
                p = clampi((int)rintf(__fmul_rn(__fdiv_rn((float)ea, sf), 255.f)), 0, 255);
            }
        }
        plut[row*32 + l] = (uint8_t)p;
    }
    __syncthreads();

    // ---- idx -> prob, word-wise in place ----
    #pragma unroll
    for(int rr = 0; rr < 2; rr++){
        int r = 2*warp + rr;
        const uint8_t* pl = plut + r*32;
        for(int wd = lane; wd < (KNpad>>2); wd += 32){
            unsigned v = *(unsigned*)&sP[r*SPB_PITCH + wd*4];
            unsigned o =  (unsigned)pl[v & 31]
                       | ((unsigned)pl[(v>>8)  & 31] << 8)
                       | ((unsigned)pl[(v>>16) & 31] << 16)
                       | ((unsigned)pl[(v>>24) & 31] << 24);
            *(unsigned*)&sP[r*SPB_PITCH + wd*4] = o;
        }
    }
    __syncthreads();

    // ---- AV via u8 x s8 MMA, V^T from global ----
    int nt = warp & 3, half = warp >> 2;
    int dim = nt*8 + g;
    const int* vt = (const int*)(g_vt) + bh*((T/4)*HD);
    int dacc[4] = {0,0,0,0};
    int nch32 = KNpad >> 5;
    for(int c32 = half; c32 < nch32; c32 += 2){
        unsigned A[4];
        A[0] = *(unsigned*)&sP[g*SPB_PITCH     + c32*32 + tg*4];
        A[1] = *(unsigned*)&sP[(g+8)*SPB_PITCH + c32*32 + tg*4];
        A[2] = *(unsigned*)&sP[g*SPB_PITCH     + c32*32 + 16 + tg*4];
        A[3] = *(unsigned*)&sP[(g+8)*SPB_PITCH + c32*32 + 16 + tg*4];
        int Bv[2];
        Bv[0] = vt[(c32*8 + tg)*32 + dim];
        Bv[1] = vt[(c32*8 + 4 + tg)*32 + dim];
        mma_u8s8(dacc, A, Bv);
    }
    if(half == 1){
        sred[g*36     + nt*8 + 2*tg]     = dacc[0];
        sred[g*36     + nt*8 + 2*tg + 1] = dacc[1];
        sred[(g+8)*36 + nt*8 + 2*tg]     = dacc[2];
        sred[(g+8)*36 + nt*8 + 2*tg + 1] = dacc[3];
    }
    __syncthreads();
    if(half == 0){
        int v0 = dacc[0] + sred[g*36     + nt*8 + 2*tg];
        int v1 = dacc[1] + sred[g*36     + nt*8 + 2*tg + 1];
        int v2 = dacc[2] + sred[(g+8)*36 + nt*8 + 2*tg];
        int v3 = dacc[3] + sred[(g+8)*36 + nt*8 + 2*tg + 1];
        int o0 = wrap8(v0>>8)&0xff, o1 = wrap8(v1>>8)&0xff;
        int o2 = wrap8(v2>>8)&0xff, o3 = wrap8(v3>>8)&0xff;
        *(uint16_t*)(g_a + (base+qb+g)*64   + h*32 + nt*8 + 2*tg) = (uint16_t)(o0 | (o1<<8));
        *(uint16_t*)(g_a + (base+qb+g+8)*64 + h*32 + nt*8 + 2*tg) = (uint16_t)(o2 | (o3<<8));
    }
}

// ---------------- fused oproj+residual+rmsnorm+FFN+residual via MMA ----------------
__global__ __launch_bounds__(256) void ffn_fused_kernel(int layer){
    __shared__ int      sa[16*17];
    __shared__ uint8_t  sxb[16*64];
    __shared__ uint8_t  shb[16*68];
    __shared__ uint8_t  sub[16*260];
    int tid = threadIdx.x, warp = tid>>5, lane = tid&31;
    int g = lane>>2, tg = lane&3;
    int bt0 = blockIdx.x*16;

    {
        int tok = tid>>4, i = tid&15;
        sa[tok*17+i] = ((const int*)g_a)[(bt0+tok)*16 + i];
    }
    __syncthreads();

    {   // oproj
        int a[2][4];
        #pragma unroll
        for(int kc=0;kc<2;kc++){
            a[kc][0] = sa[g*17     + kc*8 + tg];
            a[kc][1] = sa[(g+8)*17 + kc*8 + tg];
            a[kc][2] = sa[g*17     + kc*8 + 4 + tg];
            a[kc][3] = sa[(g+8)*17 + kc*8 + 4 + tg];
        }
        const int* wo = (const int*)(g_wo + layer*D*D);
        int c = warp*8 + g;
        int d[4] = {0,0,0,0};
        #pragma unroll
        for(int kc=0;kc<2;kc++){
            int b[2] = { wo[c*16 + kc*8 + tg], wo[c*16 + kc*8 + 4 + tg] };
            mma_s8s8(d, a[kc], b);
        }
        int o0 = warp*8 + 2*tg;
        int r0 = clampi(d[0]>>6,-128,127), r1 = clampi(d[1]>>6,-128,127);
        int r2 = clampi(d[2]>>6,-128,127), r3 = clampi(d[3]>>6,-128,127);
        sxb[g*64 + o0]       = (uint8_t)(wrap8((int)g_x[(bt0+g)*64 + o0]     + r0) & 0xff);
        sxb[g*64 + o0+1]     = (uint8_t)(wrap8((int)g_x[(bt0+g)*64 + o0+1]   + r1) & 0xff);
        sxb[(g+8)*64 + o0]   = (uint8_t)(wrap8((int)g_x[(bt0+g+8)*64 + o0]   + r2) & 0xff);
        sxb[(g+8)*64 + o0+1] = (uint8_t)(wrap8((int)g_x[(bt0+g+8)*64 + o0+1] + r3) & 0xff);
    }
    __syncthreads();

    {   // rmsnorm
        const int* gm = g_gff + layer*D;
        #pragma unroll
        for(int t=0;t<2;t++){
            int tok = 2*warp + t;
            int x0 = (int)(int8_t)sxb[tok*64 + 2*lane];
            int x1 = (int)(int8_t)sxb[tok*64 + 2*lane+1];
            int y0,y1;
            rms_pair(x0,x1,gm[2*lane],gm[2*lane+1],y0,y1);
            shb[tok*68 + 2*lane]   = (uint8_t)(y0 & 0xff);
            shb[tok*68 + 2*lane+1] = (uint8_t)(y1 & 0xff);
        }
    }
    __syncthreads();

    {   // up + relu
        const int* shi = (const int*)shb;
        int a[2][4];
        #pragma unroll
        for(int kc=0;kc<2;kc++){
            a[kc][0] = shi[g*17     + kc*8 + tg];
            a[kc][1] = shi[(g+8)*17 + kc*8 + tg];
            a[kc][2] = shi[g*17     + kc*8 + 4 + tg];
            a[kc][3] = shi[(g+8)*17 + kc*8 + 4 + tg];
        }
        const int* wu = (const int*)(g_wup + layer*DFF*D);
        #pragma unroll
        for(int nt=0;nt<4;nt++){
            int colb = warp*32 + nt*8;
            int c = colb + g;
            int d[4] = {0,0,0,0};
            #pragma unroll
            for(int kc=0;kc<2;kc++){
                int b[2] = { wu[c*16 + kc*8 + tg], wu[c*16 + kc*8 + 4 + tg] };
                mma_s8s8(d, a[kc], b);
            }
            int c0 = colb + 2*tg;
            int u0 = max(clampi(d[0]>>6,-128,127),0), u1 = max(clampi(d[1]>>6,-128,127),0);
            int u2 = max(clampi(d[2]>>6,-128,127),0), u3 = max(clampi(d[3]>>6,-128,127),0);
            sub[g*260 + c0]       = (uint8_t)u0;
            sub[g*260 + c0+1]     = (uint8_t)u1;
            sub[(g+8)*260 + c0]   = (uint8_t)u2;
            sub[(g+8)*260 + c0+1] = (uint8_t)u3;
        }
    }
    __syncthreads();

    {   // down (K=256)
        const int* sui = (const int*)sub;
        const int* wd = (const int*)(g_wdn + layer*D*DFF);
        int c = warp*8 + g;
        int d[4] = {0,0,0,0};
        #pragma unroll
        for(int kc=0;kc<8;kc++){
            int a[4];
            a[0] = sui[g*65     + kc*8 + tg];
            a[1] = sui[(g+8)*65 + kc*8 + tg];
            a[2] = sui[g*65     + kc*8 + 4 + tg];
            a[3] = sui[(g+8)*65 + kc*8 + 4 + tg];
            int b[2] = { wd[c*64 + kc*8 + tg], wd[c*64 + kc*8 + 4 + tg] };
            mma_s8s8(d, a, b);
        }
        int o0 = warp*8 + 2*tg;
        int r0 = clampi(d[0]>>6,-128,127), r1 = clampi(d[1]>>6,-128,127);
        int r2 = clampi(d[2]>>6,-128,127), r3 = clampi(d[3]>>6,-128,127);
        g_x[(bt0+g)*64 + o0]     = (int8_t)wrap8((int)(int8_t)sxb[g*64 + o0]       + r0);
        g_x[(bt0+g)*64 + o0+1]   = (int8_t)wrap8((int)(int8_t)sxb[g*64 + o0+1]     + r1);
        g_x[(bt0+g+8)*64 + o0]   = (int8_t)wrap8((int)(int8_t)sxb[(g+8)*64 + o0]   + r2);
        g_x[(bt0+g+8)*64 + o0+1] = (int8_t)wrap8((int)(int8_t)sxb[(g+8)*64 + o0+1] + r3);
    }
}

// ---------------- logits via IMMA ----------------
__global__ __launch_bounds__(256) void logits_mma_kernel(float* __restrict__ out){
    int warp = threadIdx.x>>5, lane = threadIdx.x&31;
    int g = lane>>2, tg = lane&3;
    int vbase = blockIdx.x*256 + warp*32;
    int mbase = blockIdx.y*64;

    int bhi[4][2][2], blo[4][2][2];
    #pragma unroll
    for(int nt=0;nt<4;nt++){
        int col = vbase + nt*8 + g;
        const int8_t*  eh = g_ehi + col*64;
        const uint8_t* el = g_elo + col*64;
        #pragma unroll
        for(int kc=0;kc<2;kc++){
            bhi[nt][kc][0] = *(const int*)(eh + kc*32 + tg*4);
            bhi[nt][kc][1] = *(const int*)(eh + kc*32 + 16 + tg*4);
            blo[nt][kc][0] = *(const int*)(el + kc*32 + tg*4);
            blo[nt][kc][1] = *(const int*)(el + kc*32 + 16 + tg*4);
        }
    }
    #pragma unroll
    for(int mt=0;mt<4;mt++){
        int row0 = mbase + mt*16 + g;
        const int8_t* h0 = g_h + row0*64;
        const int8_t* h8 = g_h + (row0+8)*64;
        int a[2][4];
        #pragma unroll
        for(int kc=0;kc<2;kc++){
            a[kc][0] = *(const int*)(h0 + kc*32 + tg*4);
            a[kc][1] = *(const int*)(h8 + kc*32 + tg*4);
            a[kc][2] = *(const int*)(h0 + kc*32 + 16 + tg*4);
            a[kc][3] = *(const int*)(h8 + kc*32 + 16 + tg*4);
        }
        #pragma unroll
        for(int nt=0;nt<4;nt++){
            int dh[4]={0,0,0,0}, dl[4]={0,0,0,0};
            #pragma unroll
            for(int kc=0;kc<2;kc++){
                mma_s8s8(dh, a[kc], bhi[nt][kc]);
                mma_s8u8(dl, a[kc], blo[nt][kc]);
            }
            int col = vbase + nt*8 + 2*tg;
            float2 v0, v1;
            v0.x = __fmul_rn((float)(dh[0]*256+dl[0]), 1.220703125e-4f);
            v0.y = __fmul_rn((float)(dh[1]*256+dl[1]), 1.220703125e-4f);
            v1.x = __fmul_rn((float)(dh[2]*256+dl[2]), 1.220703125e-4f);
            v1.y = __fmul_rn((float)(dh[3]*256+dl[3]), 1.220703125e-4f);
            *(float2*)(out + (size_t)row0*VOCAB + col)     = v0;
            *(float2*)(out + (size_t)(row0+8)*VOCAB + col) = v1;
        }
    }
}

// ---------------- launch ----------------
extern "C" void kernel_launch(void* const* d_in, const int* in_sizes, int n_in,
                              void* d_out, int out_size){
    const int*   tokens  = (const int*)  d_in[0];
    const float* tok_emb = (const float*)d_in[1];
    const float* pos_emb = (const float*)d_in[2];
    const float* attn_nw = (const float*)d_in[3];
    const float* qw      = (const float*)d_in[4];
    const float* kw      = (const float*)d_in[5];
    const float* vw      = (const float*)d_in[6];
    const float* ow      = (const float*)d_in[7];
    const float* ff_nw   = (const float*)d_in[8];
    const float* up      = (const float*)d_in[9];
    const float* dn      = (const float*)d_in[10];
    const float* fin_nw  = (const float*)d_in[11];
    float* out = (float*)d_out;

    cudaFuncSetAttribute(attn_fused_kernel,
                         cudaFuncAttributeMaxDynamicSharedMemorySize, ATTN_SMEM);

    prep_all<<<24 + (VOCAB*D+255)/256, 256>>>(qw,kw,vw,ow,up,dn,
                                              tok_emb, attn_nw, ff_nw, fin_nw);
    embed_kernel<<<(BT*D+255)/256,256>>>(tokens, tok_emb, pos_emb);

    for(int l=0;l<NL;l++){
        qkv_norm_kernel<<<BT/16,256>>>(l);
        attn_fused_kernel<<<dim3(T/16, BATCH*H),256,ATTN_SMEM>>>();
        ffn_fused_kernel<<<BT/16,256>>>(l);
    }
    rmsnorm_final_kernel<<<BT/8,256>>>();
    logits_mma_kernel<<<dim3(VOCAB/256, BT/64),256>>>(out);
}

// round 11
// speedup vs baseline: 1.1900x; 1.1006x over previous
#include <cuda_runtime.h>
#include <cstdint>
#include <climits>

#define BATCH 4
#define T 1024
#define D 64
#define H 2
#define HD 32
#define DFF 256
#define NL 4
#define VOCAB 8192
#define BT (BATCH*T)

// ---------------- device scratch (no allocs allowed) ----------------
__device__ __align__(16) int8_t  g_x[BT*D];
__device__ __align__(16) int8_t  g_h[BT*D];
__device__ __align__(16) int8_t  g_q[BT*D];
__device__ __align__(16) int8_t  g_k[BT*D];
__device__ __align__(16) int8_t  g_a[BT*D];
__device__ __align__(16) int8_t  g_vt[BATCH*H*(T/4)*HD*4];  // V transposed quad-packed
__device__ __align__(16) int8_t  g_wq[NL*D*D], g_wk[NL*D*D], g_wv[NL*D*D], g_wo[NL*D*D];
__device__ __align__(16) int8_t  g_wup[NL*DFF*D], g_wdn[NL*D*DFF];
__device__ __align__(16) int     g_gattn[NL*D], g_gff[NL*D], g_gfin[D];
__device__ __align__(16) int8_t  g_ehi[VOCAB*D];
__device__ __align__(16) uint8_t g_elo[VOCAB*D];

// ---------------- helpers ----------------
__device__ __forceinline__ int wrap8(int v){ return (int)(signed char)(v & 0xff); }
__device__ __forceinline__ int clampi(int v,int lo,int hi){ return min(max(v,lo),hi); }
__device__ __forceinline__ int gammaq(float w){
    float c = fminf(fmaxf(w,-2.f),2.f);
    float r = rintf(__fmul_rn(c,1024.f));
    return clampi((int)r,-32768,32767);
}
__device__ __forceinline__ void rms_pair(int x0,int x1,int g0,int g1,int& y0,int& y1){
    int ss = x0*x0 + x1*x1;
    #pragma unroll
    for(int o=16;o>0;o>>=1) ss += __shfl_xor_sync(0xffffffffu, ss, o);
    int mean_sq = ss >> 6;
    int lut = min(mean_sq >> 6, 255);
    float bc = (float)(lut*64 + 32);
    int inv = clampi((int)rintf(__fdiv_rn(16384.f, __fsqrt_rn(bc))), 0, 16383);
    int p0 = (x0*inv) >> 8, p1 = (x1*inv) >> 8;
    y0 = clampi((int)floorf(__fmul_rn(__fmul_rn((float)p0,(float)g0), 0.0009765625f)),-128,127);
    y1 = clampi((int)floorf(__fmul_rn(__fmul_rn((float)p1,(float)g1), 0.0009765625f)),-128,127);
}
// m16n8k32 int8 MMA
__device__ __forceinline__ void mma_s8s8(int* d, const int* a, const int* b){
    asm("mma.sync.aligned.m16n8k32.row.col.s32.s8.s8.s32 "
        "{%0,%1,%2,%3},{%4,%5,%6,%7},{%8,%9},{%0,%1,%2,%3};"
        : "+r"(d[0]),"+r"(d[1]),"+r"(d[2]),"+r"(d[3])
        : "r"(a[0]),"r"(a[1]),"r"(a[2]),"r"(a[3]),"r"(b[0]),"r"(b[1]));
}
__device__ __forceinline__ void mma_s8u8(int* d, const int* a, const int* b){
    asm("mma.sync.aligned.m16n8k32.row.col.s32.s8.u8.s32 "
        "{%0,%1,%2,%3},{%4,%5,%6,%7},{%8,%9},{%0,%1,%2,%3};"
        : "+r"(d[0]),"+r"(d[1]),"+r"(d[2]),"+r"(d[3])
        : "r"(a[0]),"r"(a[1]),"r"(a[2]),"r"(a[3]),"r"(b[0]),"r"(b[1]));
}
__device__ __forceinline__ void mma_u8s8(int* d, const unsigned* a, const int* b){
    asm("mma.sync.aligned.m16n8k32.row.col.s32.u8.s8.s32 "
        "{%0,%1,%2,%3},{%4,%5,%6,%7},{%8,%9},{%0,%1,%2,%3};"
        : "+r"(d[0]),"+r"(d[1]),"+r"(d[2]),"+r"(d[3])
        : "r"(a[0]),"r"(a[1]),"r"(a[2]),"r"(a[3]),"r"(b[0]),"r"(b[1]));
}
__device__ __forceinline__ int ea_of_idx(int l){
    return (l<16) ? l : (l<21 ? 64+11*(l-21) : (l<=24 ? 256+64*(l-24) : 0));
}

// ---------------- merged prep ----------------
__global__ void prep_all(const float* qw, const float* kw, const float* vw,
                         const float* ow, const float* up, const float* dn,
                         const float* tok_emb, const float* attn_nw,
                         const float* ff_nw, const float* fin_nw){
    int m = blockIdx.x;
    if(m < 24){
        const float* src; int8_t* dst; int n;
        if(m < 16){
            int l = m >> 2, wsel = m & 3; n = D*D;
            const float* bases[4] = {qw,kw,vw,ow};
            int8_t* dsts[4] = {g_wq,g_wk,g_wv,g_wo};
            src = bases[wsel] + l*n; dst = dsts[wsel] + l*n;
        } else if(m < 20){ int l=m-16; n=DFF*D; src=up+l*n; dst=g_wup+l*n; }
        else             { int l=m-20; n=D*DFF; src=dn+l*n; dst=g_wdn+l*n; }

        __shared__ float red[256];
        float s = 0.f;
        for(int i=threadIdx.x;i<n;i+=256) s += fabsf(src[i]);
        red[threadIdx.x]=s; __syncthreads();
        for(int o=128;o>0;o>>=1){ if(threadIdx.x<o) red[threadIdx.x]+=red[threadIdx.x+o]; __syncthreads(); }
        float scale = fmaxf(__fdiv_rn(red[0], (float)n), 1e-5f);
        for(int i=threadIdx.x;i<n;i+=256){
            float t = rintf(__fdiv_rn(src[i], scale));
            t = fminf(fmaxf(t,-1.f),1.f);
            dst[i] = (int8_t)(int)t;
        }
        return;
    }
    int i = (m-24)*256 + threadIdx.x;
    if(i < VOCAB*D){
        float r = rintf(__fmul_rn(tok_emb[i],1024.f));
        int q = clampi((int)r,-32768,32767);
        g_ehi[i] = (int8_t)(q >> 8);
        g_elo[i] = (uint8_t)(q & 0xff);
    }
    if(m == 24){
        int t=threadIdx.x;
        for(int j=t;j<NL*D;j+=256){
            g_gattn[j] = gammaq(attn_nw[j]);
            g_gff[j]   = gammaq(ff_nw[j]);
        }
        if(t<D) g_gfin[t] = gammaq(fin_nw[t]);
    }
}

// ---------------- token+pos embedding ----------------
__global__ void embed_kernel(const int* tokens, const float* tok_emb, const float* pos_emb){
    int i = blockIdx.x*256 + threadIdx.x;
    if(i >= BT*D) return;
    int bt = i >> 6, d = i & 63;
    int t = bt & (T-1);
    int tok = tokens[bt];
    int tq = clampi((int)rintf(__fmul_rn(tok_emb[tok*D+d],1024.f)),-32768,32767);
    int pq = clampi((int)rintf(__fmul_rn(pos_emb[t*D+d],1024.f)),-32768,32767);
    g_x[i] = (int8_t)wrap8((tq+pq) >> 3);
}

// ---------------- final rmsnorm ----------------
__global__ void rmsnorm_final_kernel(){
    int row  = (blockIdx.x*blockDim.x + threadIdx.x) >> 5;
    int lane = threadIdx.x & 31;
    if(row >= BT) return;
    const int8_t* r = g_x + row*D;
    int x0 = r[lane*2], x1 = r[lane*2+1];
    int y0,y1;
    rms_pair(x0,x1,g_gfin[lane*2],g_gfin[lane*2+1],y0,y1);
    g_h[row*D+lane*2]   = (int8_t)y0;
    g_h[row*D+lane*2+1] = (int8_t)y1;
}

// ---------------- fused rmsnorm + QKV via MMA (V written transposed) ----------------
__global__ __launch_bounds__(256) void qkv_norm_kernel(int layer){
    __shared__ uint8_t shb[16*68];
    int tid = threadIdx.x, warp = tid>>5, lane = tid&31;
    int g = lane>>2, tg = lane&3;
    int bt0 = blockIdx.x*16;
    const int* gm = g_gattn + layer*D;
    #pragma unroll
    for(int t=0;t<2;t++){
        int tok = 2*warp + t;
        const int8_t* xr = g_x + (bt0+tok)*D;
        int x0 = xr[2*lane], x1 = xr[2*lane+1];
        int y0,y1;
        rms_pair(x0,x1,gm[2*lane],gm[2*lane+1],y0,y1);
        shb[tok*68 + 2*lane]   = (uint8_t)(y0 & 0xff);
        shb[tok*68 + 2*lane+1] = (uint8_t)(y1 & 0xff);
    }
    __syncthreads();
    const int* shi = (const int*)shb;
    int a[2][4];
    #pragma unroll
    for(int kc=0;kc<2;kc++){
        a[kc][0] = shi[g*17     + kc*8 + tg];
        a[kc][1] = shi[(g+8)*17 + kc*8 + tg];
        a[kc][2] = shi[g*17     + kc*8 + 4 + tg];
        a[kc][3] = shi[(g+8)*17 + kc*8 + 4 + tg];
    }
    const int* wq = (const int*)(g_wq + layer*D*D);
    const int* wk = (const int*)(g_wk + layer*D*D);
    const int* wv = (const int*)(g_wv + layer*D*D);
    #pragma unroll
    for(int nt=0;nt<3;nt++){
        const int* wb = (nt==0) ? wq : (nt==1 ? wk : wv);
        int c = warp*8 + g;
        int d[4] = {0,0,0,0};
        #pragma unroll
        for(int kc=0;kc<2;kc++){
            int b[2] = { wb[c*16 + kc*8 + tg], wb[c*16 + kc*8 + 4 + tg] };
            mma_s8s8(d, a[kc], b);
        }
        int o0 = warp*8 + 2*tg;
        int v0 = clampi(d[0]>>6,-128,127), v1 = clampi(d[1]>>6,-128,127);
        int v2 = clampi(d[2]>>6,-128,127), v3 = clampi(d[3]>>6,-128,127);
        if(nt < 2){
            int8_t* dst = (nt==0) ? g_q : g_k;
            *(uint16_t*)(dst + (bt0+g)*64   + o0) = (uint16_t)((v0&0xff) | ((v1&0xff)<<8));
            *(uint16_t*)(dst + (bt0+g+8)*64 + o0) = (uint16_t)((v2&0xff) | ((v3&0xff)<<8));
        } else {
            int bt_a = bt0 + g, bt_b = bt0 + g + 8;
            int bsel = bt_a >> 10;
            int ta = bt_a & (T-1), tb = bt_b & (T-1);
            int hh = o0 >> 5, hd = o0 & 31;
            int8_t* vtb = g_vt + (bsel*2 + hh)*((T/4)*HD*4);
            vtb[(ta>>2)*128 + hd*4     + (ta&3)] = (int8_t)v0;
            vtb[(ta>>2)*128 + (hd+1)*4 + (ta&3)] = (int8_t)v1;
            vtb[(tb>>2)*128 + hd*4     + (tb&3)] = (int8_t)v2;
            vtb[(tb>>2)*128 + (hd+1)*4 + (tb&3)] = (int8_t)v3;
        }
    }
}

// ---------------- attention: two-pass MMA scores + LUT softmax + MMA AV ----------------
#define SPB_PITCH 1040   // bytes per prob row

__global__ __launch_bounds__(256) void attn_fused_kernel(){
    __shared__ uint8_t sP[16*SPB_PITCH];   // idx bytes -> probs in place
    __shared__ uint8_t plut[16*32];
    __shared__ int rowmax[16];
    __shared__ int rowsum[16];
    __shared__ int sred[16*36];

    int tid = threadIdx.x, warp = tid>>5, lane = tid&31;
    int g = lane>>2, tg = lane&3;
    int qt = gridDim.x - 1 - blockIdx.x;     // LPT: biggest tiles first
    int bh = blockIdx.y, b = bh>>1, h = bh&1;
    int qb = qt*16, base = b*T;
    int KN = qb + 16, nch = KN >> 3;
    int KNpad = (KN + 31) & ~31;

    if(tid < 16){ rowmax[tid] = INT_MIN; rowsum[tid] = 0; }
    __syncthreads();

    // A-fragments from global Q (16 queries x head_dim 32)
    const int* qp = (const int*)g_q;
    int aq[4];
    aq[0] = qp[(base+qb+g)*16   + h*8 + tg];
    aq[1] = qp[(base+qb+g+8)*16 + h*8 + tg];
    aq[2] = qp[(base+qb+g)*16   + h*8 + 4 + tg];
    aq[3] = qp[(base+qb+g+8)*16 + h*8 + 4 + tg];
    const int* kp = (const int*)g_k;
    int r0 = qb + g, r8 = qb + g + 8;

    // ---- pass A: row maxima (no score storage) ----
    {
        int mg = INT_MIN, mg8 = INT_MIN;
        for(int c = warp; c < nch; c += 8){
            int k0 = c*8;
            int bv[2];
            bv[0] = kp[(base+k0+g)*16 + h*8 + tg];
            bv[1] = kp[(base+k0+g)*16 + h*8 + 4 + tg];
            int d[4] = {0,0,0,0};
            mma_s8s8(d, aq, bv);
            int c0 = k0 + 2*tg;
            int s0 = (int)floorf(__fmul_rn(__int2float_rn(d[0]*45), 0.00390625f));
            int s1 = (int)floorf(__fmul_rn(__int2float_rn(d[1]*45), 0.00390625f));
            int s2 = (int)floorf(__fmul_rn(__int2float_rn(d[2]*45), 0.00390625f));
            int s3 = (int)floorf(__fmul_rn(__int2float_rn(d[3]*45), 0.00390625f));
            if(c0   > r0) s0 = -32767;
            if(c0+1 > r0) s1 = -32767;
            if(c0   > r8) s2 = -32767;
            if(c0+1 > r8) s3 = -32767;
            mg  = max(mg,  max(s0,s1));
            mg8 = max(mg8, max(s2,s3));
        }
        mg  = max(mg,  __shfl_xor_sync(0xffffffffu, mg , 1));
        mg  = max(mg,  __shfl_xor_sync(0xffffffffu, mg , 2));
        mg8 = max(mg8, __shfl_xor_sync(0xffffffffu, mg8, 1));
        mg8 = max(mg8, __shfl_xor_sync(0xffffffffu, mg8, 2));
        if(tg == 0){
            atomicMax(&rowmax[g],   mg);
            atomicMax(&rowmax[g+8], mg8);
        }
    }
    __syncthreads();

    // ---- pass B: recompute scores -> idx bytes + ea-sums ----
    {
        int m_g = rowmax[g], m_g8 = rowmax[g+8];
        int ea_l = ea_of_idx(lane);
        int su_g = 0, su_g8 = 0;
        for(int c = warp; c < nch; c += 8){
            int k0 = c*8;
            int bv[2];
            bv[0] = kp[(base+k0+g)*16 + h*8 + tg];
            bv[1] = kp[(base+k0+g)*16 + h*8 + 4 + tg];
            int d[4] = {0,0,0,0};
            mma_s8s8(d, aq, bv);
            int c0 = k0 + 2*tg;
            int s0 = (int)floorf(__fmul_rn(__int2float_rn(d[0]*45), 0.00390625f));
            int s1 = (int)floorf(__fmul_rn(__int2float_rn(d[1]*45), 0.00390625f));
            int s2 = (int)floorf(__fmul_rn(__int2float_rn(d[2]*45), 0.00390625f));
            int s3 = (int)floorf(__fmul_rn(__int2float_rn(d[3]*45), 0.00390625f));
            if(c0   > r0) s0 = -32767;
            if(c0+1 > r0) s1 = -32767;
            if(c0   > r8) s2 = -32767;
            if(c0+1 > r8) s3 = -32767;
            int i0 = max(s0 - m_g  + 24, 0);
            int i1 = max(s1 - m_g  + 24, 0);
            int i2 = max(s2 - m_g8 + 24, 0);
            int i3 = max(s3 - m_g8 + 24, 0);
            su_g  += __shfl_sync(0xffffffffu, ea_l, i0) + __shfl_sync(0xffffffffu, ea_l, i1);
            su_g8 += __shfl_sync(0xffffffffu, ea_l, i2) + __shfl_sync(0xffffffffu, ea_l, i3);
            *(uint16_t*)&sP[g*SPB_PITCH + c0]     = (uint16_t)(i0 | (i1<<8));
            *(uint16_t*)&sP[(g+8)*SPB_PITCH + c0] = (uint16_t)(i2 | (i3<<8));
        }
        su_g  += __shfl_xor_sync(0xffffffffu, su_g, 1);
        su_g  += __shfl_xor_sync(0xffffffffu, su_g, 2);
        su_g8 += __shfl_xor_sync(0xffffffffu, su_g8, 1);
        su_g8 += __shfl_xor_sync(0xffffffffu, su_g8, 2);
        if(tg == 0){
            atomicAdd(&rowsum[g],   su_g);
            atomicAdd(&rowsum[g+8], su_g8);
        }
    }
    // zero pad idx bytes (KN..KNpad): idx 0 -> ea 0 -> p 0
    if(KNpad > KN && tid < 64){
        int row = tid >> 2, wsel = tid & 3;
        *(unsigned*)&sP[row*SPB_PITCH + KN + wsel*4] = 0;
    }
    __syncthreads();

    // ---- per-row prob LUT (exact fdiv chain, 25 entries/row) ----
    for(int e = tid; e < 512; e += 256){
        int row = e>>5, l = e&31;
        int p = 0;
        if(l <= 24){
            int ea = ea_of_idx(l);
            if(ea > 0){
                float sf = (float)max(rowsum[row], 1);
                p = clampi((int)rintf(__fmul_rn(__fdiv_rn((float)ea, sf), 255.f)), 0, 255);
            }
        }
        plut[row*32 + l] = (uint8_t)p;
    }
    __syncthreads();

    // ---- idx -> prob, word-wise in place ----
    #pragma unroll
    for(int rr = 0; rr < 2; rr++){
        int r = 2*warp + rr;
        const uint8_t* pl = plut + r*32;
        for(int wd = lane; wd < (KNpad>>2); wd += 32){
            unsigned v = *(unsigned*)&sP[r*SPB_PITCH + wd*4];
            unsigned o =  (unsigned)pl[v & 31]
                       | ((unsigned)pl[(v>>8)  & 31] << 8)
                       | ((unsigned)pl[(v>>16) & 31] << 16)
                       | ((unsigned)pl[(v>>24) & 31] << 24);
            *(unsigned*)&sP[r*SPB_PITCH + wd*4] = o;
        }
    }
    __syncthreads();

    // ---- AV via u8 x s8 MMA, V^T from global ----
    int nt = warp & 3, half = warp >> 2;
    int dim = nt*8 + g;
    const int* vt = (const int*)(g_vt) + bh*((T/4)*HD);
    int dacc[4] = {0,0,0,0};
    int nch32 = KNpad >> 5;
    for(int c32 = half; c32 < nch32; c32 += 2){
        unsigned A[4];
        A[0] = *(unsigned*)&sP[g*SPB_PITCH     + c32*32 + tg*4];
        A[1] = *(unsigned*)&sP[(g+8)*SPB_PITCH + c32*32 + tg*4];
        A[2] = *(unsigned*)&sP[g*SPB_PITCH     + c32*32 + 16 + tg*4];
        A[3] = *(unsigned*)&sP[(g+8)*SPB_PITCH + c32*32 + 16 + tg*4];
        int Bv[2];
        Bv[0] = vt[(c32*8 + tg)*32 + dim];
        Bv[1] = vt[(c32*8 + 4 + tg)*32 + dim];
        mma_u8s8(dacc, A, Bv);
    }
    if(half == 1){
        sred[g*36     + nt*8 + 2*tg]     = dacc[0];
        sred[g*36     + nt*8 + 2*tg + 1] = dacc[1];
        sred[(g+8)*36 + nt*8 + 2*tg]     = dacc[2];
        sred[(g+8)*36 + nt*8 + 2*tg + 1] = dacc[3];
    }
    __syncthreads();
    if(half == 0){
        int v0 = dacc[0] + sred[g*36     + nt*8 + 2*tg];
        int v1 = dacc[1] + sred[g*36     + nt*8 + 2*tg + 1];
        int v2 = dacc[2] + sred[(g+8)*36 + nt*8 + 2*tg];
        int v3 = dacc[3] + sred[(g+8)*36 + nt*8 + 2*tg + 1];
        int o0 = wrap8(v0>>8)&0xff, o1 = wrap8(v1>>8)&0xff;
        int o2 = wrap8(v2>>8)&0xff, o3 = wrap8(v3>>8)&0xff;
        *(uint16_t*)(g_a + (base+qb+g)*64   + h*32 + nt*8 + 2*tg) = (uint16_t)(o0 | (o1<<8));
        *(uint16_t*)(g_a + (base+qb+g+8)*64 + h*32 + nt*8 + 2*tg) = (uint16_t)(o2 | (o3<<8));
    }
}

// ---------------- fused oproj+residual+rmsnorm+FFN+residual via MMA ----------------
__global__ __launch_bounds__(256) void ffn_fused_kernel(int layer){
    __shared__ int      sa[16*17];
    __shared__ uint8_t  sxb[16*64];
    __shared__ uint8_t  shb[16*68];
    __shared__ uint8_t  sub[16*260];
    int tid = threadIdx.x, warp = tid>>5, lane = tid&31;
    int g = lane>>2, tg = lane&3;
    int bt0 = blockIdx.x*16;

    {
        int tok = tid>>4, i = tid&15;
        sa[tok*17+i] = ((const int*)g_a)[(bt0+tok)*16 + i];
    }
    __syncthreads();

    {   // oproj
        int a[2][4];
        #pragma unroll
        for(int kc=0;kc<2;kc++){
            a[kc][0] = sa[g*17     + kc*8 + tg];
            a[kc][1] = sa[(g+8)*17 + kc*8 + tg];
            a[kc][2] = sa[g*17     + kc*8 + 4 + tg];
            a[kc][3] = sa[(g+8)*17 + kc*8 + 4 + tg];
        }
        const int* wo = (const int*)(g_wo + layer*D*D);
        int c = warp*8 + g;
        int d[4] = {0,0,0,0};
        #pragma unroll
        for(int kc=0;kc<2;kc++){
            int b[2] = { wo[c*16 + kc*8 + tg], wo[c*16 + kc*8 + 4 + tg] };
            mma_s8s8(d, a[kc], b);
        }
        int o0 = warp*8 + 2*tg;
        int r0 = clampi(d[0]>>6,-128,127), r1 = clampi(d[1]>>6,-128,127);
        int r2 = clampi(d[2]>>6,-128,127), r3 = clampi(d[3]>>6,-128,127);
        sxb[g*64 + o0]       = (uint8_t)(wrap8((int)g_x[(bt0+g)*64 + o0]     + r0) & 0xff);
        sxb[g*64 + o0+1]     = (uint8_t)(wrap8((int)g_x[(bt0+g)*64 + o0+1]   + r1) & 0xff);
        sxb[(g+8)*64 + o0]   = (uint8_t)(wrap8((int)g_x[(bt0+g+8)*64 + o0]   + r2) & 0xff);
        sxb[(g+8)*64 + o0+1] = (uint8_t)(wrap8((int)g_x[(bt0+g+8)*64 + o0+1] + r3) & 0xff);
    }
    __syncthreads();

    {   // rmsnorm
        const int* gm = g_gff + layer*D;
        #pragma unroll
        for(int t=0;t<2;t++){
            int tok = 2*warp + t;
            int x0 = (int)(int8_t)sxb[tok*64 + 2*lane];
            int x1 = (int)(int8_t)sxb[tok*64 + 2*lane+1];
            int y0,y1;
            rms_pair(x0,x1,gm[2*lane],gm[2*lane+1],y0,y1);
            shb[tok*68 + 2*lane]   = (uint8_t)(y0 & 0xff);
            shb[tok*68 + 2*lane+1] = (uint8_t)(y1 & 0xff);
        }
    }
    __syncthreads();

    {   // up + relu
        const int* shi = (const int*)shb;
        int a[2][4];
        #pragma unroll
        for(int kc=0;kc<2;kc++){
            a[kc][0] = shi[g*17     + kc*8 + tg];
            a[kc][1] = shi[(g+8)*17 + kc*8 + tg];
            a[kc][2] = shi[g*17     + kc*8 + 4 + tg];
            a[kc][3] = shi[(g+8)*17 + kc*8 + 4 + tg];
        }
        const int* wu = (const int*)(g_wup + layer*DFF*D);
        #pragma unroll
        for(int nt=0;nt<4;nt++){
            int colb = warp*32 + nt*8;
            int c = colb + g;
            int d[4] = {0,0,0,0};
            #pragma unroll
            for(int kc=0;kc<2;kc++){
                int b[2] = { wu[c*16 + kc*8 + tg], wu[c*16 + kc*8 + 4 + tg] };
                mma_s8s8(d, a[kc], b);
            }
            int c0 = colb + 2*tg;
            int u0 = max(clampi(d[0]>>6,-128,127),0), u1 = max(clampi(d[1]>>6,-128,127),0);
            int u2 = max(clampi(d[2]>>6,-128,127),0), u3 = max(clampi(d[3]>>6,-128,127),0);
            sub[g*260 + c0]       = (uint8_t)u0;
            sub[g*260 + c0+1]     = (uint8_t)u1;
            sub[(g+8)*260 + c0]   = (uint8_t)u2;
            sub[(g+8)*260 + c0+1] = (uint8_t)u3;
        }
    }
    __syncthreads();

    {   // down (K=256)
        const int* sui = (const int*)sub;
        const int* wd = (const int*)(g_wdn + layer*D*DFF);
        int c = warp*8 + g;
        int d[4] = {0,0,0,0};
        #pragma unroll
        for(int kc=0;kc<8;kc++){
            int a[4];
            a[0] = sui[g*65     + kc*8 + tg];
            a[1] = sui[(g+8)*65 + kc*8 + tg];
            a[2] = sui[g*65     + kc*8 + 4 + tg];
            a[3] = sui[(g+8)*65 + kc*8 + 4 + tg];
            int b[2] = { wd[c*64 + kc*8 + tg], wd[c*64 + kc*8 + 4 + tg] };
            mma_s8s8(d, a, b);
        }
        int o0 = warp*8 + 2*tg;
        int r0 = clampi(d[0]>>6,-128,127), r1 = clampi(d[1]>>6,-128,127);
        int r2 = clampi(d[2]>>6,-128,127), r3 = clampi(d[3]>>6,-128,127);
        g_x[(bt0+g)*64 + o0]     = (int8_t)wrap8((int)(int8_t)sxb[g*64 + o0]       + r0);
        g_x[(bt0+g)*64 + o0+1]   = (int8_t)wrap8((int)(int8_t)sxb[g*64 + o0+1]     + r1);
        g_x[(bt0+g+8)*64 + o0]   = (int8_t)wrap8((int)(int8_t)sxb[(g+8)*64 + o0]   + r2);
        g_x[(bt0+g+8)*64 + o0+1] = (int8_t)wrap8((int)(int8_t)sxb[(g+8)*64 + o0+1] + r3);
    }
}

// ---------------- logits via IMMA ----------------
__global__ __launch_bounds__(256) void logits_mma_kernel(float* __restrict__ out){
    int warp = threadIdx.x>>5, lane = threadIdx.x&31;
    int g = lane>>2, tg = lane&3;
    int vbase = blockIdx.x*256 + warp*32;
    int mbase = blockIdx.y*64;

    int bhi[4][2][2], blo[4][2][2];
    #pragma unroll
    for(int nt=0;nt<4;nt++){
        int col = vbase + nt*8 + g;
        const int8_t*  eh = g_ehi + col*64;
        const uint8_t* el = g_elo + col*64;
        #pragma unroll
        for(int kc=0;kc<2;kc++){
            bhi[nt][kc][0] = *(const int*)(eh + kc*32 + tg*4);
            bhi[nt][kc][1] = *(const int*)(eh + kc*32 + 16 + tg*4);
            blo[nt][kc][0] = *(const int*)(el + kc*32 + tg*4);
            blo[nt][kc][1] = *(const int*)(el + kc*32 + 16 + tg*4);
        }
    }
    #pragma unroll
    for(int mt=0;mt<4;mt++){
        int row0 = mbase + mt*16 + g;
        const int8_t* h0 = g_h + row0*64;
        const int8_t* h8 = g_h + (row0+8)*64;
        int a[2][4];
        #pragma unroll
        for(int kc=0;kc<2;kc++){
            a[kc][0] = *(const int*)(h0 + kc*32 + tg*4);
            a[kc][1] = *(const int*)(h8 + kc*32 + tg*4);
            a[kc][2] = *(const int*)(h0 + kc*32 + 16 + tg*4);
            a[kc][3] = *(const int*)(h8 + kc*32 + 16 + tg*4);
        }
        #pragma unroll
        for(int nt=0;nt<4;nt++){
            int dh[4]={0,0,0,0}, dl[4]={0,0,0,0};
            #pragma unroll
            for(int kc=0;kc<2;kc++){
                mma_s8s8(dh, a[kc], bhi[nt][kc]);
                mma_s8u8(dl, a[kc], blo[nt][kc]);
            }
            int col = vbase + nt*8 + 2*tg;
            float2 v0, v1;
            v0.x = __fmul_rn((float)(dh[0]*256+dl[0]), 1.220703125e-4f);
            v0.y = __fmul_rn((float)(dh[1]*256+dl[1]), 1.220703125e-4f);
            v1.x = __fmul_rn((float)(dh[2]*256+dl[2]), 1.220703125e-4f);
            v1.y = __fmul_rn((float)(dh[3]*256+dl[3]), 1.220703125e-4f);
            *(float2*)(out + (size_t)row0*VOCAB + col)     = v0;
            *(float2*)(out + (size_t)(row0+8)*VOCAB + col) = v1;
        }
    }
}

// ---------------- launch ----------------
extern "C" void kernel_launch(void* const* d_in, const int* in_sizes, int n_in,
                              void* d_out, int out_size){
    const int*   tokens  = (const int*)  d_in[0];
    const float* tok_emb = (const float*)d_in[1];
    const float* pos_emb = (const float*)d_in[2];
    const float* attn_nw = (const float*)d_in[3];
    const float* qw      = (const float*)d_in[4];
    const float* kw      = (const float*)d_in[5];
    const float* vw      = (const float*)d_in[6];
    const float* ow      = (const float*)d_in[7];
    const float* ff_nw   = (const float*)d_in[8];
    const float* up      = (const float*)d_in[9];
    const float* dn      = (const float*)d_in[10];
    const float* fin_nw  = (const float*)d_in[11];
    float* out = (float*)d_out;

    prep_all<<<24 + (VOCAB*D+255)/256, 256>>>(qw,kw,vw,ow,up,dn,
                                              tok_emb, attn_nw, ff_nw, fin_nw);
    embed_kernel<<<(BT*D+255)/256,256>>>(tokens, tok_emb, pos_emb);

    for(int l=0;l<NL;l++){
        qkv_norm_kernel<<<BT/16,256>>>(l);
        attn_fused_kernel<<<dim3(T/16, BATCH*H),256>>>();
        ffn_fused_kernel<<<BT/16,256>>>(l);
    }
    rmsnorm_final_kernel<<<BT/8,256>>>();
    logits_mma_kernel<<<dim3(VOCAB/256, BT/64),256>>>(out);
}

// round 12
// speedup vs baseline: 1.2510x; 1.0513x over previous
#include <cuda_runtime.h>
#include <cstdint>
#include <climits>

#define BATCH 4
#define T 1024
#define D 64
#define H 2
#define HD 32
#define DFF 256
#define NL 4
#define VOCAB 8192
#define BT (BATCH*T)

// ---------------- device scratch (no allocs allowed) ----------------
__device__ __align__(16) int8_t  g_x[BT*D];
__device__ __align__(16) int8_t  g_h[BT*D];
__device__ __align__(16) int8_t  g_q[BT*D];
__device__ __align__(16) int8_t  g_k[BT*D];
__device__ __align__(16) int8_t  g_a[BT*D];
__device__ __align__(16) int8_t  g_vt[BATCH*H*(T/4)*HD*4];
__device__ __align__(16) int8_t  g_wq[NL*D*D], g_wk[NL*D*D], g_wv[NL*D*D], g_wo[NL*D*D];
__device__ __align__(16) int8_t  g_wup[NL*DFF*D], g_wdn[NL*D*DFF];
__device__ __align__(16) int     g_gattn[NL*D], g_gff[NL*D], g_gfin[D];
__device__ __align__(16) int8_t  g_ehi[VOCAB*D];
__device__ __align__(16) uint8_t g_elo[VOCAB*D];

// ---------------- helpers ----------------
__device__ __forceinline__ int wrap8(int v){ return (int)(signed char)(v & 0xff); }
__device__ __forceinline__ int clampi(int v,int lo,int hi){ return min(max(v,lo),hi); }
__device__ __forceinline__ int gammaq(float w){
    float c = fminf(fmaxf(w,-2.f),2.f);
    float r = rintf(__fmul_rn(c,1024.f));
    return clampi((int)r,-32768,32767);
}
__device__ __forceinline__ void rms_pair(int x0,int x1,int g0,int g1,int& y0,int& y1){
    int ss = x0*x0 + x1*x1;
    #pragma unroll
    for(int o=16;o>0;o>>=1) ss += __shfl_xor_sync(0xffffffffu, ss, o);
    int mean_sq = ss >> 6;
    int lut = min(mean_sq >> 6, 255);
    float bc = (float)(lut*64 + 32);
    int inv = clampi((int)rintf(__fdiv_rn(16384.f, __fsqrt_rn(bc))), 0, 16383);
    int p0 = (x0*inv) >> 8, p1 = (x1*inv) >> 8;
    y0 = clampi((int)floorf(__fmul_rn(__fmul_rn((float)p0,(float)g0), 0.0009765625f)),-128,127);
    y1 = clampi((int)floorf(__fmul_rn(__fmul_rn((float)p1,(float)g1), 0.0009765625f)),-128,127);
}
__device__ __forceinline__ void mma_s8s8(int* d, const int* a, const int* b){
    asm("mma.sync.aligned.m16n8k32.row.col.s32.s8.s8.s32 "
        "{%0,%1,%2,%3},{%4,%5,%6,%7},{%8,%9},{%0,%1,%2,%3};"
        : "+r"(d[0]),"+r"(d[1]),"+r"(d[2]),"+r"(d[3])
        : "r"(a[0]),"r"(a[1]),"r"(a[2]),"r"(a[3]),"r"(b[0]),"r"(b[1]));
}
__device__ __forceinline__ void mma_s8u8(int* d, const int* a, const int* b){
    asm("mma.sync.aligned.m16n8k32.row.col.s32.s8.u8.s32 "
        "{%0,%1,%2,%3},{%4,%5,%6,%7},{%8,%9},{%0,%1,%2,%3};"
        : "+r"(d[0]),"+r"(d[1]),"+r"(d[2]),"+r"(d[3])
        : "r"(a[0]),"r"(a[1]),"r"(a[2]),"r"(a[3]),"r"(b[0]),"r"(b[1]));
}
__device__ __forceinline__ void mma_u8s8(int* d, const unsigned* a, const int* b){
    asm("mma.sync.aligned.m16n8k32.row.col.s32.u8.s8.s32 "
        "{%0,%1,%2,%3},{%4,%5,%6,%7},{%8,%9},{%0,%1,%2,%3};"
        : "+r"(d[0]),"+r"(d[1]),"+r"(d[2]),"+r"(d[3])
        : "r"(a[0]),"r"(a[1]),"r"(a[2]),"r"(a[3]),"r"(b[0]),"r"(b[1]));
}
__device__ __forceinline__ int ea_of_idx(int l){
    return (l<16) ? l : (l<21 ? 64+11*(l-21) : (l<=24 ? 256+64*(l-24) : 0));
}
// score epilogue: s = floor(rn(d*45) * 2^-8), with causal mask
__device__ __forceinline__ void score4(const int* d, int c0, int r0, int r8, int* s){
    s[0] = (int)floorf(__fmul_rn(__int2float_rn(d[0]*45), 0.00390625f));
    s[1] = (int)floorf(__fmul_rn(__int2float_rn(d[1]*45), 0.00390625f));
    s[2] = (int)floorf(__fmul_rn(__int2float_rn(d[2]*45), 0.00390625f));
    s[3] = (int)floorf(__fmul_rn(__int2float_rn(d[3]*45), 0.00390625f));
    if(c0   > r0) s[0] = -32767;
    if(c0+1 > r0) s[1] = -32767;
    if(c0   > r8) s[2] = -32767;
    if(c0+1 > r8) s[3] = -32767;
}

// ---------------- merged prep ----------------
__global__ void prep_all(const float* qw, const float* kw, const float* vw,
                         const float* ow, const float* up, const float* dn,
                         const float* tok_emb, const float* attn_nw,
                         const float* ff_nw, const float* fin_nw){
    int m = blockIdx.x;
    if(m < 24){
        const float* src; int8_t* dst; int n;
        if(m < 16){
            int l = m >> 2, wsel = m & 3; n = D*D;
            const float* bases[4] = {qw,kw,vw,ow};
            int8_t* dsts[4] = {g_wq,g_wk,g_wv,g_wo};
            src = bases[wsel] + l*n; dst = dsts[wsel] + l*n;
        } else if(m < 20){ int l=m-16; n=DFF*D; src=up+l*n; dst=g_wup+l*n; }
        else             { int l=m-20; n=D*DFF; src=dn+l*n; dst=g_wdn+l*n; }

        __shared__ float red[256];
        float s = 0.f;
        for(int i=threadIdx.x;i<n;i+=256) s += fabsf(src[i]);
        red[threadIdx.x]=s; __syncthreads();
        for(int o=128;o>0;o>>=1){ if(threadIdx.x<o) red[threadIdx.x]+=red[threadIdx.x+o]; __syncthreads(); }
        float scale = fmaxf(__fdiv_rn(red[0], (float)n), 1e-5f);
        for(int i=threadIdx.x;i<n;i+=256){
            float t = rintf(__fdiv_rn(src[i], scale));
            t = fminf(fmaxf(t,-1.f),1.f);
            dst[i] = (int8_t)(int)t;
        }
        return;
    }
    int i = (m-24)*256 + threadIdx.x;
    if(i < VOCAB*D){
        float r = rintf(__fmul_rn(tok_emb[i],1024.f));
        int q = clampi((int)r,-32768,32767);
        g_ehi[i] = (int8_t)(q >> 8);
        g_elo[i] = (uint8_t)(q & 0xff);
    }
    if(m == 24){
        int t=threadIdx.x;
        for(int j=t;j<NL*D;j+=256){
            g_gattn[j] = gammaq(attn_nw[j]);
            g_gff[j]   = gammaq(ff_nw[j]);
        }
        if(t<D) g_gfin[t] = gammaq(fin_nw[t]);
    }
}

// ---- shared qkv tail: rmsnorm(sx2, gamma) -> shb, then QKV MMAs (layer) ----
__device__ __forceinline__ void qkv_tail(const uint8_t* sx2, uint8_t* shb, int layer,
                                         int bt0, int warp, int lane, int g, int tg){
    const int* gm = g_gattn + layer*D;
    #pragma unroll
    for(int t=0;t<2;t++){
        int tok = 2*warp + t;
        int x0 = (int)(int8_t)sx2[tok*68 + 2*lane];
        int x1 = (int)(int8_t)sx2[tok*68 + 2*lane+1];
        int y0,y1;
        rms_pair(x0,x1,gm[2*lane],gm[2*lane+1],y0,y1);
        shb[tok*68 + 2*lane]   = (uint8_t)(y0 & 0xff);
        shb[tok*68 + 2*lane+1] = (uint8_t)(y1 & 0xff);
    }
    __syncthreads();
    const int* shi = (const int*)shb;
    int a[2][4];
    #pragma unroll
    for(int kc=0;kc<2;kc++){
        a[kc][0] = shi[g*17     + kc*8 + tg];
        a[kc][1] = shi[(g+8)*17 + kc*8 + tg];
        a[kc][2] = shi[g*17     + kc*8 + 4 + tg];
        a[kc][3] = shi[(g+8)*17 + kc*8 + 4 + tg];
    }
    const int* wq = (const int*)(g_wq + layer*D*D);
    const int* wk = (const int*)(g_wk + layer*D*D);
    const int* wv = (const int*)(g_wv + layer*D*D);
    #pragma unroll
    for(int nt=0;nt<3;nt++){
        const int* wb = (nt==0) ? wq : (nt==1 ? wk : wv);
        int c = warp*8 + g;
        int d[4] = {0,0,0,0};
        #pragma unroll
        for(int kc=0;kc<2;kc++){
            int b[2] = { wb[c*16 + kc*8 + tg], wb[c*16 + kc*8 + 4 + tg] };
            mma_s8s8(d, a[kc], b);
        }
        int o0 = warp*8 + 2*tg;
        int v0 = clampi(d[0]>>6,-128,127), v1 = clampi(d[1]>>6,-128,127);
        int v2 = clampi(d[2]>>6,-128,127), v3 = clampi(d[3]>>6,-128,127);
        if(nt < 2){
            int8_t* dst = (nt==0) ? g_q : g_k;
            *(uint16_t*)(dst + (bt0+g)*64   + o0) = (uint16_t)((v0&0xff) | ((v1&0xff)<<8));
            *(uint16_t*)(dst + (bt0+g+8)*64 + o0) = (uint16_t)((v2&0xff) | ((v3&0xff)<<8));
        } else {
            int bt_a = bt0 + g, bt_b = bt0 + g + 8;
            int bsel = bt_a >> 10;
            int ta = bt_a & (T-1), tb = bt_b & (T-1);
            int hh = o0 >> 5, hd = o0 & 31;
            int8_t* vtb = g_vt + (bsel*2 + hh)*((T/4)*HD*4);
            vtb[(ta>>2)*128 + hd*4     + (ta&3)] = (int8_t)v0;
            vtb[(ta>>2)*128 + (hd+1)*4 + (ta&3)] = (int8_t)v1;
            vtb[(tb>>2)*128 + hd*4     + (tb&3)] = (int8_t)v2;
            vtb[(tb>>2)*128 + (hd+1)*4 + (tb&3)] = (int8_t)v3;
        }
    }
}

// ---------------- embed + qkv(0), 16 tokens per block ----------------
__global__ __launch_bounds__(256) void embed_qkv_kernel(const int* tokens,
                                                        const float* tok_emb,
                                                        const float* pos_emb){
    __shared__ uint8_t sx2[16*68];
    __shared__ uint8_t shb[16*68];
    int tid = threadIdx.x, warp = tid>>5, lane = tid&31;
    int g = lane>>2, tg = lane&3;
    int bt0 = blockIdx.x*16;
    for(int idx = tid; idx < 16*64; idx += 256){
        int bt = bt0 + (idx>>6), d = idx & 63;
        int t = bt & (T-1);
        int tok = tokens[bt];
        int tq = clampi((int)rintf(__fmul_rn(tok_emb[tok*D+d],1024.f)),-32768,32767);
        int pq = clampi((int)rintf(__fmul_rn(pos_emb[t*D+d],1024.f)),-32768,32767);
        int xv = wrap8((tq+pq) >> 3);
        g_x[bt*D + d] = (int8_t)xv;
        sx2[(idx>>6)*68 + d] = (uint8_t)(xv & 0xff);
    }
    __syncthreads();
    qkv_tail(sx2, shb, 0, bt0, warp, lane, g, tg);
}

// ---------------- attention: two-pass MMA scores (ILP x2) + LUT softmax + MMA AV ----------------
#define SPB_PITCH 1040

__global__ __launch_bounds__(256) void attn_fused_kernel(){
    __shared__ uint8_t sP[16*SPB_PITCH];
    __shared__ uint8_t plut[16*32];
    __shared__ int rowmax[16];
    __shared__ int rowsum[16];
    __shared__ int sred[16*36];

    int tid = threadIdx.x, warp = tid>>5, lane = tid&31;
    int g = lane>>2, tg = lane&3;
    int qt = gridDim.x - 1 - blockIdx.x;     // LPT
    int bh = blockIdx.y, b = bh>>1, h = bh&1;
    int qb = qt*16, base = b*T;
    int KN = qb + 16, nch = KN >> 3;         // nch always even
    int KNpad = (KN + 31) & ~31;

    if(tid < 16){ rowmax[tid] = INT_MIN; rowsum[tid] = 0; }
    __syncthreads();

    const int* qp = (const int*)g_q;
    int aq[4];
    aq[0] = qp[(base+qb+g)*16   + h*8 + tg];
    aq[1] = qp[(base+qb+g+8)*16 + h*8 + tg];
    aq[2] = qp[(base+qb+g)*16   + h*8 + 4 + tg];
    aq[3] = qp[(base+qb+g+8)*16 + h*8 + 4 + tg];
    const int* kp = (const int*)g_k;
    int r0 = qb + g, r8 = qb + g + 8;

    // ---- pass A: row maxima (2 chunks in flight) ----
    {
        int mg = INT_MIN, mg8 = INT_MIN;
        for(int c = warp; c < nch; c += 16){
            int k0 = c*8;
            bool has2 = (c+8) < nch;
            int bv0[2] = { kp[(base+k0+g)*16 + h*8 + tg], kp[(base+k0+g)*16 + h*8 + 4 + tg] };
            int d0[4] = {0,0,0,0}, d1[4] = {0,0,0,0};
            mma_s8s8(d0, aq, bv0);
            if(has2){
                int k1 = k0 + 64;
                int bv1[2] = { kp[(base+k1+g)*16 + h*8 + tg], kp[(base+k1+g)*16 + h*8 + 4 + tg] };
                mma_s8s8(d1, aq, bv1);
            }
            int s0[4], s1[4];
            score4(d0, k0 + 2*tg, r0, r8, s0);
            mg  = max(mg,  max(s0[0],s0[1]));
            mg8 = max(mg8, max(s0[2],s0[3]));
            if(has2){
                score4(d1, k0 + 64 + 2*tg, r0, r8, s1);
                mg  = max(mg,  max(s1[0],s1[1]));
                mg8 = max(mg8, max(s1[2],s1[3]));
            }
        }
        mg  = max(mg,  __shfl_xor_sync(0xffffffffu, mg , 1));
        mg  = max(mg,  __shfl_xor_sync(0xffffffffu, mg , 2));
        mg8 = max(mg8, __shfl_xor_sync(0xffffffffu, mg8, 1));
        mg8 = max(mg8, __shfl_xor_sync(0xffffffffu, mg8, 2));
        if(tg == 0){
            atomicMax(&rowmax[g],   mg);
            atomicMax(&rowmax[g+8], mg8);
        }
    }
    __syncthreads();

    // ---- pass B: recompute -> idx bytes + ea-sums (2 chunks in flight) ----
    {
        int m_g = rowmax[g], m_g8 = rowmax[g+8];
        int ea_l = ea_of_idx(lane);
        int su_g = 0, su_g8 = 0;
        for(int c = warp; c < nch; c += 16){
            int k0 = c*8;
            bool has2 = (c+8) < nch;
            int bv0[2] = { kp[(base+k0+g)*16 + h*8 + tg], kp[(base+k0+g)*16 + h*8 + 4 + tg] };
            int d0[4] = {0,0,0,0}, d1[4] = {0,0,0,0};
            mma_s8s8(d0, aq, bv0);
            if(has2){
                int k1 = k0 + 64;
                int bv1[2] = { kp[(base+k1+g)*16 + h*8 + tg], kp[(base+k1+g)*16 + h*8 + 4 + tg] };
                mma_s8s8(d1, aq, bv1);
            }
            #pragma unroll
            for(int u=0;u<2;u++){
                if(u==1 && !has2) break;
                int* dd = u ? d1 : d0;
                int c0 = k0 + u*64 + 2*tg;
                int s[4];
                score4(dd, c0, r0, r8, s);
                int i0 = max(s[0] - m_g  + 24, 0);
                int i1 = max(s[1] - m_g  + 24, 0);
                int i2 = max(s[2] - m_g8 + 24, 0);
                int i3 = max(s[3] - m_g8 + 24, 0);
                su_g  += __shfl_sync(0xffffffffu, ea_l, i0) + __shfl_sync(0xffffffffu, ea_l, i1);
                su_g8 += __shfl_sync(0xffffffffu, ea_l, i2) + __shfl_sync(0xffffffffu, ea_l, i3);
                *(uint16_t*)&sP[g*SPB_PITCH + c0]     = (uint16_t)(i0 | (i1<<8));
                *(uint16_t*)&sP[(g+8)*SPB_PITCH + c0] = (uint16_t)(i2 | (i3<<8));
            }
        }
        su_g  += __shfl_xor_sync(0xffffffffu, su_g, 1);
        su_g  += __shfl_xor_sync(0xffffffffu, su_g, 2);
        su_g8 += __shfl_xor_sync(0xffffffffu, su_g8, 1);
        su_g8 += __shfl_xor_sync(0xffffffffu, su_g8, 2);
        if(tg == 0){
            atomicAdd(&rowsum[g],   su_g);
            atomicAdd(&rowsum[g+8], su_g8);
        }
    }
    if(KNpad > KN && tid < 64){
        int row = tid >> 2, wsel = tid & 3;
        *(unsigned*)&sP[row*SPB_PITCH + KN + wsel*4] = 0;
    }
    __syncthreads();

    // ---- per-row prob LUT ----
    for(int e = tid; e < 512; e += 256){
        int row = e>>5, l = e&31;
        int p = 0;
        if(l <= 24){
            int ea = ea_of_idx(l);
            if(ea > 0){
                float sf = (float)max(rowsum[row], 1);
                p = clampi((int)rintf(__fmul_rn(__fdiv_rn((float)ea, sf), 255.f)), 0, 255);
            }
        }
        plut[row*32 + l] = (uint8_t)p;
    }
    __syncthreads();

    // ---- idx -> prob, word-wise in place ----
    #pragma unroll
    for(int rr = 0; rr < 2; rr++){
        int r = 2*warp + rr;
        const uint8_t* pl = plut + r*32;
        for(int wd = lane; wd < (KNpad>>2); wd += 32){
            unsigned v = *(unsigned*)&sP[r*SPB_PITCH + wd*4];
            unsigned o =  (unsigned)pl[v & 31]
                       | ((unsigned)pl[(v>>8)  & 31] << 8)
                       | ((unsigned)pl[(v>>16) & 31] << 16)
                       | ((unsigned)pl[(v>>24) & 31] << 24);
            *(unsigned*)&sP[r*SPB_PITCH + wd*4] = o;
        }
    }
    __syncthreads();

    // ---- AV via u8 x s8 MMA ----
    int nt = warp & 3, half = warp >> 2;
    int dim = nt*8 + g;
    const int* vt = (const int*)(g_vt) + bh*((T/4)*HD);
    int dacc[4] = {0,0,0,0};
    int nch32 = KNpad >> 5;
    for(int c32 = half; c32 < nch32; c32 += 2){
        unsigned A[4];
        A[0] = *(unsigned*)&sP[g*SPB_PITCH     + c32*32 + tg*4];
        A[1] = *(unsigned*)&sP[(g+8)*SPB_PITCH + c32*32 + tg*4];
        A[2] = *(unsigned*)&sP[g*SPB_PITCH     + c32*32 + 16 + tg*4];
        A[3] = *(unsigned*)&sP[(g+8)*SPB_PITCH + c32*32 + 16 + tg*4];
        int Bv[2];
        Bv[0] = vt[(c32*8 + tg)*32 + dim];
        Bv[1] = vt[(c32*8 + 4 + tg)*32 + dim];
        mma_u8s8(dacc, A, Bv);
    }
    if(half == 1){
        sred[g*36     + nt*8 + 2*tg]     = dacc[0];
        sred[g*36     + nt*8 + 2*tg + 1] = dacc[1];
        sred[(g+8)*36 + nt*8 + 2*tg]     = dacc[2];
        sred[(g+8)*36 + nt*8 + 2*tg + 1] = dacc[3];
    }
    __syncthreads();
    if(half == 0){
        int v0 = dacc[0] + sred[g*36     + nt*8 + 2*tg];
        int v1 = dacc[1] + sred[g*36     + nt*8 + 2*tg + 1];
        int v2 = dacc[2] + sred[(g+8)*36 + nt*8 + 2*tg];
        int v3 = dacc[3] + sred[(g+8)*36 + nt*8 + 2*tg + 1];
        int o0 = wrap8(v0>>8)&0xff, o1 = wrap8(v1>>8)&0xff;
        int o2 = wrap8(v2>>8)&0xff, o3 = wrap8(v3>>8)&0xff;
        *(uint16_t*)(g_a + (base+qb+g)*64   + h*32 + nt*8 + 2*tg) = (uint16_t)(o0 | (o1<<8));
        *(uint16_t*)(g_a + (base+qb+g+8)*64 + h*32 + nt*8 + 2*tg) = (uint16_t)(o2 | (o3<<8));
    }
}

// ---------------- fused oproj+res+rmsnorm+FFN+res, then qkv(layer+1) or final rmsnorm ----------------
__global__ __launch_bounds__(256) void ffn_qkv_kernel(int layer){
    __shared__ int      sa[16*17];
    __shared__ uint8_t  sxb[16*64];
    __shared__ uint8_t  shb[16*68];
    __shared__ uint8_t  sub[16*260];
    __shared__ uint8_t  sx2[16*68];
    int tid = threadIdx.x, warp = tid>>5, lane = tid&31;
    int g = lane>>2, tg = lane&3;
    int bt0 = blockIdx.x*16;

    {
        int tok = tid>>4, i = tid&15;
        sa[tok*17+i] = ((const int*)g_a)[(bt0+tok)*16 + i];
    }
    __syncthreads();

    {   // oproj + residual
        int a[2][4];
        #pragma unroll
        for(int kc=0;kc<2;kc++){
            a[kc][0] = sa[g*17     + kc*8 + tg];
            a[kc][1] = sa[(g+8)*17 + kc*8 + tg];
            a[kc][2] = sa[g*17     + kc*8 + 4 + tg];
            a[kc][3] = sa[(g+8)*17 + kc*8 + 4 + tg];
        }
        const int* wo = (const int*)(g_wo + layer*D*D);
        int c = warp*8 + g;
        int d[4] = {0,0,0,0};
        #pragma unroll
        for(int kc=0;kc<2;kc++){
            int b[2] = { wo[c*16 + kc*8 + tg], wo[c*16 + kc*8 + 4 + tg] };
            mma_s8s8(d, a[kc], b);
        }
        int o0 = warp*8 + 2*tg;
        int r0 = clampi(d[0]>>6,-128,127), r1 = clampi(d[1]>>6,-128,127);
        int r2 = clampi(d[2]>>6,-128,127), r3 = clampi(d[3]>>6,-128,127);
        sxb[g*64 + o0]       = (uint8_t)(wrap8((int)g_x[(bt0+g)*64 + o0]     + r0) & 0xff);
        sxb[g*64 + o0+1]     = (uint8_t)(wrap8((int)g_x[(bt0+g)*64 + o0+1]   + r1) & 0xff);
        sxb[(g+8)*64 + o0]   = (uint8_t)(wrap8((int)g_x[(bt0+g+8)*64 + o0]   + r2) & 0xff);
        sxb[(g+8)*64 + o0+1] = (uint8_t)(wrap8((int)g_x[(bt0+g+8)*64 + o0+1] + r3) & 0xff);
    }
    __syncthreads();

    {   // ffn rmsnorm
        const int* gm = g_gff + layer*D;
        #pragma unroll
        for(int t=0;t<2;t++){
            int tok = 2*warp + t;
            int x0 = (int)(int8_t)sxb[tok*64 + 2*lane];
            int x1 = (int)(int8_t)sxb[tok*64 + 2*lane+1];
            int y0,y1;
            rms_pair(x0,x1,gm[2*lane],gm[2*lane+1],y0,y1);
            shb[tok*68 + 2*lane]   = (uint8_t)(y0 & 0xff);
            shb[tok*68 + 2*lane+1] = (uint8_t)(y1 & 0xff);
        }
    }
    __syncthreads();

    {   // up + relu
        const int* shi = (const int*)shb;
        int a[2][4];
        #pragma unroll
        for(int kc=0;kc<2;kc++){
            a[kc][0] = shi[g*17     + kc*8 + tg];
            a[kc][1] = shi[(g+8)*17 + kc*8 + tg];
            a[kc][2] = shi[g*17     + kc*8 + 4 + tg];
            a[kc][3] = shi[(g+8)*17 + kc*8 + 4 + tg];
        }
        const int* wu = (const int*)(g_wup + layer*DFF*D);
        #pragma unroll
        for(int nt=0;nt<4;nt++){
            int colb = warp*32 + nt*8;
            int c = colb + g;
            int d[4] = {0,0,0,0};
            #pragma unroll
            for(int kc=0;kc<2;kc++){
                int b[2] = { wu[c*16 + kc*8 + tg], wu[c*16 + kc*8 + 4 + tg] };
                mma_s8s8(d, a[kc], b);
            }
            int c0 = colb + 2*tg;
            int u0 = max(clampi(d[0]>>6,-128,127),0), u1 = max(clampi(d[1]>>6,-128,127),0);
            int u2 = max(clampi(d[2]>>6,-128,127),0), u3 = max(clampi(d[3]>>6,-128,127),0);
            sub[g*260 + c0]       = (uint8_t)u0;
            sub[g*260 + c0+1]     = (uint8_t)u1;
            sub[(g+8)*260 + c0]   = (uint8_t)u2;
            sub[(g+8)*260 + c0+1] = (uint8_t)u3;
        }
    }
    __syncthreads();

    {   // down (K=256) + residual -> sx2, g_x
        const int* sui = (const int*)sub;
        const int* wd = (const int*)(g_wdn + layer*D*DFF);
        int c = warp*8 + g;
        int d[4] = {0,0,0,0};
        #pragma unroll
        for(int kc=0;kc<8;kc++){
            int a[4];
            a[0] = sui[g*65     + kc*8 + tg];
            a[1] = sui[(g+8)*65 + kc*8 + tg];
            a[2] = sui[g*65     + kc*8 + 4 + tg];
            a[3] = sui[(g+8)*65 + kc*8 + 4 + tg];
            int b[2] = { wd[c*64 + kc*8 + tg], wd[c*64 + kc*8 + 4 + tg] };
            mma_s8s8(d, a, b);
        }
        int o0 = warp*8 + 2*tg;
        int r0 = clampi(d[0]>>6,-128,127), r1 = clampi(d[1]>>6,-128,127);
        int r2 = clampi(d[2]>>6,-128,127), r3 = clampi(d[3]>>6,-128,127);
        int x0 = wrap8((int)(int8_t)sxb[g*64 + o0]       + r0);
        int x1 = wrap8((int)(int8_t)sxb[g*64 + o0+1]     + r1);
        int x2 = wrap8((int)(int8_t)sxb[(g+8)*64 + o0]   + r2);
        int x3 = wrap8((int)(int8_t)sxb[(g+8)*64 + o0+1] + r3);
        g_x[(bt0+g)*64 + o0]     = (int8_t)x0;
        g_x[(bt0+g)*64 + o0+1]   = (int8_t)x1;
        g_x[(bt0+g+8)*64 + o0]   = (int8_t)x2;
        g_x[(bt0+g+8)*64 + o0+1] = (int8_t)x3;
        sx2[g*68 + o0]       = (uint8_t)(x0 & 0xff);
        sx2[g*68 + o0+1]     = (uint8_t)(x1 & 0xff);
        sx2[(g+8)*68 + o0]   = (uint8_t)(x2 & 0xff);
        sx2[(g+8)*68 + o0+1] = (uint8_t)(x3 & 0xff);
    }
    __syncthreads();

    if(layer + 1 < NL){
        qkv_tail(sx2, shb, layer+1, bt0, warp, lane, g, tg);
    } else {
        // final rmsnorm -> g_h
        const int* gm = g_gfin;
        #pragma unroll
        for(int t=0;t<2;t++){
            int tok = 2*warp + t;
            int x0 = (int)(int8_t)sx2[tok*68 + 2*lane];
            int x1 = (int)(int8_t)sx2[tok*68 + 2*lane+1];
            int y0,y1;
            rms_pair(x0,x1,gm[2*lane],gm[2*lane+1],y0,y1);
            g_h[(bt0+tok)*D + 2*lane]   = (int8_t)y0;
            g_h[(bt0+tok)*D + 2*lane+1] = (int8_t)y1;
        }
    }
}

// ---------------- logits via IMMA ----------------
__global__ __launch_bounds__(256) void logits_mma_kernel(float* __restrict__ out){
    int warp = threadIdx.x>>5, lane = threadIdx.x&31;
    int g = lane>>2, tg = lane&3;
    int vbase = blockIdx.x*256 + warp*32;
    int mbase = blockIdx.y*64;

    int bhi[4][2][2], blo[4][2][2];
    #pragma unroll
    for(int nt=0;nt<4;nt++){
        int col = vbase + nt*8 + g;
        const int8_t*  eh = g_ehi + col*64;
        const uint8_t* el = g_elo + col*64;
        #pragma unroll
        for(int kc=0;kc<2;kc++){
            bhi[nt][kc][0] = *(const int*)(eh + kc*32 + tg*4);
            bhi[nt][kc][1] = *(const int*)(eh + kc*32 + 16 + tg*4);
            blo[nt][kc][0] = *(const int*)(el + kc*32 + tg*4);
            blo[nt][kc][1] = *(const int*)(el + kc*32 + 16 + tg*4);
        }
    }
    #pragma unroll
    for(int mt=0;mt<4;mt++){
        int row0 = mbase + mt*16 + g;
        const int8_t* h0 = g_h + row0*64;
        const int8_t* h8 = g_h + (row0+8)*64;
        int a[2][4];
        #pragma unroll
        for(int kc=0;kc<2;kc++){
            a[kc][0] = *(const int*)(h0 + kc*32 + tg*4);
            a[kc][1] = *(const int*)(h8 + kc*32 + tg*4);
            a[kc][2] = *(const int*)(h0 + kc*32 + 16 + tg*4);
            a[kc][3] = *(const int*)(h8 + kc*32 + 16 + tg*4);
        }
        #pragma unroll
        for(int nt=0;nt<4;nt++){
            int dh[4]={0,0,0,0}, dl[4]={0,0,0,0};
            #pragma unroll
            for(int kc=0;kc<2;kc++){
                mma_s8s8(dh, a[kc], bhi[nt][kc]);
                mma_s8u8(dl, a[kc], blo[nt][kc]);
            }
            int col = vbase + nt*8 + 2*tg;
            float2 v0, v1;
            v0.x = __fmul_rn((float)(dh[0]*256+dl[0]), 1.220703125e-4f);
            v0.y = __fmul_rn((float)(dh[1]*256+dl[1]), 1.220703125e-4f);
            v1.x = __fmul_rn((float)(dh[2]*256+dl[2]), 1.220703125e-4f);
            v1.y = __fmul_rn((float)(dh[3]*256+dl[3]), 1.220703125e-4f);
            *(float2*)(out + (size_t)row0*VOCAB + col)     = v0;
            *(float2*)(out + (size_t)(row0+8)*VOCAB + col) = v1;
        }
    }
}

// ---------------- launch ----------------
extern "C" void kernel_launch(void* const* d_in, const int* in_sizes, int n_in,
                              void* d_out, int out_size){
    const int*   tokens  = (const int*)  d_in[0];
    const float* tok_emb = (const float*)d_in[1];
    const float* pos_emb = (const float*)d_in[2];
    const float* attn_nw = (const float*)d_in[3];
    const float* qw      = (const float*)d_in[4];
    const float* kw      = (const float*)d_in[5];
    const float* vw      = (const float*)d_in[6];
    const float* ow      = (const float*)d_in[7];
    const float* ff_nw   = (const float*)d_in[8];
    const float* up      = (const float*)d_in[9];
    const float* dn      = (const float*)d_in[10];
    const float* fin_nw  = (const float*)d_in[11];
    float* out = (float*)d_out;

    prep_all<<<24 + (VOCAB*D+255)/256, 256>>>(qw,kw,vw,ow,up,dn,
                                              tok_emb, attn_nw, ff_nw, fin_nw);
    embed_qkv_kernel<<<BT/16,256>>>(tokens, tok_emb, pos_emb);

    for(int l=0;l<NL;l++){
        attn_fused_kernel<<<dim3(T/16, BATCH*H),256>>>();
        ffn_qkv_kernel<<<BT/16,256>>>(l);
    }
    logits_mma_kernel<<<dim3(VOCAB/256, BT/64),256>>>(out);
}